// round 6
// baseline (speedup 1.0000x reference)
#include <cuda_runtime.h>
#include <math.h>
#include <stdint.h>

#define B_SZ   16384
#define C_CAM  4
#define DBB    2048
#define DH     512
#define MTOT   (B_SZ * C_CAM)

// -------- device-global scratch (no allocations allowed) --------
__device__ float g_reg[(size_t)MTOT * DH];
__device__ float g_xn [(size_t)MTOT * DH];           // LN out, k-permuted
__device__ float g_h  [(size_t)MTOT * DH];           // swiglu out, k-permuted
__device__ float g_A  [(size_t)MTOT * 36];
__device__ float g_pw [(size_t)DH * DBB];            // rna + k-permuted
__device__ float g_wg [(size_t)C_CAM * DH * DH];     // rna + k-permuted
__device__ float g_wv [(size_t)C_CAM * DH * DH];     // rna + k-permuted
__device__ float g_wo [(size_t)C_CAM * 36 * DH];     // rna + k-permuted

// -------- helpers --------
__device__ __forceinline__ unsigned f2tf(float x) {
    unsigned u; asm("cvt.rna.tf32.f32 %0, %1;" : "=r"(u) : "f"(x)); return u;
}
__device__ __forceinline__ int permk(int c) {        // c in [0,32)
    return ((c & 3) << 3) | (c >> 2);
}
__device__ __forceinline__ void mma_tf32(float d[4], const unsigned a[4], const unsigned b[2]) {
    asm volatile(
        "mma.sync.aligned.m16n8k8.row.col.f32.tf32.tf32.f32 "
        "{%0,%1,%2,%3}, {%4,%5,%6,%7}, {%8,%9}, {%0,%1,%2,%3};\n"
        : "+f"(d[0]), "+f"(d[1]), "+f"(d[2]), "+f"(d[3])
        : "r"(a[0]), "r"(a[1]), "r"(a[2]), "r"(a[3]), "r"(b[0]), "r"(b[1]));
}
__device__ __forceinline__ void cp16(float* s, const float* g) {
    unsigned a = (unsigned)__cvta_generic_to_shared(s);
    asm volatile("cp.async.cg.shared.global [%0], [%1], 16;\n" :: "r"(a), "l"(g));
}
__device__ __forceinline__ void cp_commit() { asm volatile("cp.async.commit_group;\n" ::: "memory"); }
__device__ __forceinline__ void cp_wait1()  { asm volatile("cp.async.wait_group 1;\n" ::: "memory"); }
__device__ __forceinline__ void cp_wait0()  { asm volatile("cp.async.wait_group 0;\n" ::: "memory"); }

// select float4 component with compile-time constant e (loops fully unrolled)
#define F4C(v, e) ((e) == 0 ? (v).x : (e) == 1 ? (v).y : (e) == 2 ? (v).z : (v).w)

#define LDS_ 36   // 32 + 4 pad floats; float4 frag loads stay 16B-aligned, conflict-free

// =====================================================================
// Stage 0: rna-round + k-permute all weight matrices.
// blocks 0..4095: pw (K=2048) + wg/wv (K=512); 4096..4383: wo (K=512).
// =====================================================================
__global__ __launch_bounds__(256) void round_weights(
    const float* __restrict__ pw, const float* __restrict__ wg,
    const float* __restrict__ wv, const float* __restrict__ wo)
{
    int bi = blockIdx.x;
    if (bi < 4096) {
        int idx = bi * 256 + threadIdx.x;
        {   // proj_w: rows of 2048
            int k = idx & 2047;
            int pk = (k & ~31) | permk(k & 31);
            g_pw[(idx & ~2047) | pk] = __uint_as_float(f2tf(pw[idx]));
        }
        {   // w_gate / w_val: rows of 512
            int k = idx & 511;
            int pk = (k & ~31) | permk(k & 31);
            int dst = (idx & ~511) | pk;
            g_wg[dst] = __uint_as_float(f2tf(wg[idx]));
            g_wv[dst] = __uint_as_float(f2tf(wv[idx]));
        }
    } else {
        int idx = (bi - 4096) * 256 + threadIdx.x;   // 73728 elements
        int k = idx & 511;
        int pk = (k & ~31) | permk(k & 31);
        g_wo[(idx & ~511) | pk] = __uint_as_float(f2tf(wo[idx]));
    }
}

// =====================================================================
// Stage 1: reg[65536,512] = thumb[65536,2048] @ proj_w^T + bias
// BM=128, BN=128, BK=32, 3-stage cp.async, 1 barrier/tile.
// A: raw fp32 (RZ-truncated by mma). B: pre-rounded+permuted -> LDS.128 frags.
// =====================================================================
__global__ __launch_bounds__(256, 2) void gemm1_kernel(
    const float* __restrict__ T, const float* __restrict__ bias)
{
    extern __shared__ float sm1[];
    float* As = sm1;                    // [3][128*LDS_]
    float* Bs = sm1 + 3 * 128 * LDS_;   // [3][128*LDS_] (permuted content)

    int tid  = threadIdx.x;
    int bm   = blockIdx.y * 128;
    int bn   = blockIdx.x * 128;
    int warp = tid >> 5, lane = tid & 31;
    int wr = warp >> 2, wc = warp & 3;
    int wm = wr * 64,  wn = wc * 32;
    int g = lane >> 2, t = lane & 3;

    float acc[4][4][4];
    #pragma unroll
    for (int i = 0; i < 4; i++)
        #pragma unroll
        for (int j = 0; j < 4; j++)
            #pragma unroll
            for (int k = 0; k < 4; k++) acc[i][j][k] = 0.f;

    int lrow = tid >> 3;
    int lcol = (tid & 7) * 4;
    const int NK = DBB / 32;        // 64

    #pragma unroll
    for (int s = 0; s < 2; s++) {
        float* dA = As + s * 128 * LDS_;
        float* dB = Bs + s * 128 * LDS_;
        int k0 = s * 32;
        #pragma unroll
        for (int it = 0; it < 4; it++) {
            int r = lrow + it * 32;
            cp16(&dA[r * LDS_ + lcol], T    + (size_t)(bm + r) * DBB + k0 + lcol);
            cp16(&dB[r * LDS_ + lcol], g_pw + (size_t)(bn + r) * DBB + k0 + lcol);
        }
        cp_commit();
    }

    int slot = 0, nslot = 2;
    for (int i = 0; i < NK; i++) {
        cp_wait1();
        __syncthreads();

        if (i + 2 < NK) {
            int k0 = (i + 2) * 32;
            float* dA = As + nslot * 128 * LDS_;
            float* dB = Bs + nslot * 128 * LDS_;
            #pragma unroll
            for (int it = 0; it < 4; it++) {
                int r = lrow + it * 32;
                cp16(&dA[r * LDS_ + lcol], T    + (size_t)(bm + r) * DBB + k0 + lcol);
                cp16(&dB[r * LDS_ + lcol], g_pw + (size_t)(bn + r) * DBB + k0 + lcol);
            }
        }
        cp_commit();

        const float* cA = As + slot * 128 * LDS_;
        const float* cB = Bs + slot * 128 * LDS_;
        float4 bf[4];
        #pragma unroll
        for (int j = 0; j < 4; j++) {
            int kk = j * 8;
            unsigned afr[4][4];
            #pragma unroll
            for (int mt = 0; mt < 4; mt++) {
                int r0 = wm + mt * 16;
                afr[mt][0] = __float_as_uint(cA[(r0 + g    ) * LDS_ + kk + t]);
                afr[mt][1] = __float_as_uint(cA[(r0 + 8 + g) * LDS_ + kk + t]);
                afr[mt][2] = __float_as_uint(cA[(r0 + g    ) * LDS_ + kk + t + 4]);
                afr[mt][3] = __float_as_uint(cA[(r0 + 8 + g) * LDS_ + kk + t + 4]);
            }
            if ((j & 1) == 0) {
                int off = t * 8 + (j >> 1) * 4;
                #pragma unroll
                for (int nt = 0; nt < 4; nt++)
                    bf[nt] = *(const float4*)&cB[(wn + nt * 8 + g) * LDS_ + off];
            }
            const int e = (j & 1) * 2;
            #pragma unroll
            for (int mt = 0; mt < 4; mt++)
                #pragma unroll
                for (int nt = 0; nt < 4; nt++) {
                    unsigned b2[2] = { __float_as_uint(F4C(bf[nt], e)),
                                       __float_as_uint(F4C(bf[nt], e + 1)) };
                    mma_tf32(acc[mt][nt], afr[mt], b2);
                }
        }
        slot = (slot == 2) ? 0 : slot + 1;
        nslot = (nslot == 2) ? 0 : nslot + 1;
    }

    #pragma unroll
    for (int mt = 0; mt < 4; mt++) {
        #pragma unroll
        for (int nt = 0; nt < 4; nt++) {
            int row0 = bm + wm + mt * 16 + g;
            int col  = bn + wn + nt * 8 + t * 2;
            float b0 = bias[col], b1 = bias[col + 1];
            g_reg[(size_t)row0 * DH + col]           = acc[mt][nt][0] + b0;
            g_reg[(size_t)row0 * DH + col + 1]       = acc[mt][nt][1] + b1;
            g_reg[(size_t)(row0 + 8) * DH + col]     = acc[mt][nt][2] + b0;
            g_reg[(size_t)(row0 + 8) * DH + col + 1] = acc[mt][nt][3] + b1;
        }
    }
}

// =====================================================================
// Stage 2: LayerNorm (warp/row); output rna-rounded AND k-permuted
// =====================================================================
__global__ __launch_bounds__(256) void ln_kernel(
    const float* __restrict__ gamma, const float* __restrict__ beta)
{
    int wglob = (blockIdx.x * blockDim.x + threadIdx.x) >> 5;
    int lane  = threadIdx.x & 31;
    if (wglob >= MTOT) return;
    int c = wglob & 3;
    const float* row = g_reg + (size_t)wglob * DH;
    float v[16], s = 0.f, s2 = 0.f;
    #pragma unroll
    for (int i = 0; i < 16; i++) {
        v[i] = row[lane + i * 32];
        s += v[i]; s2 += v[i] * v[i];
    }
    #pragma unroll
    for (int o = 16; o > 0; o >>= 1) {
        s  += __shfl_xor_sync(0xffffffffu, s,  o);
        s2 += __shfl_xor_sync(0xffffffffu, s2, o);
    }
    float mu   = s * (1.f / DH);
    float var  = s2 * (1.f / DH) - mu * mu;
    float rstd = rsqrtf(var + 1e-5f);
    float* orow = g_xn + (size_t)wglob * DH;
    const float* ga = gamma + c * DH;
    const float* be = beta  + c * DH;
    int pl = permk(lane);
    #pragma unroll
    for (int i = 0; i < 16; i++) {
        int k = lane + i * 32;
        float xn = (v[i] - mu) * rstd * ga[k] + be[k];
        orow[i * 32 + pl] = __uint_as_float(f2tf(xn));
    }
}

// =====================================================================
// Stage 3: per-camera dual GEMM + SwiGLU. All operands permuted -> LDS.128
// fragment loads. BM=128, BN=64, BK=32, 3-stage, 1 barrier/tile.
// =====================================================================
__global__ __launch_bounds__(256, 2) void gemm2_kernel()
{
    extern __shared__ float sm2[];
    float* As  = sm2;                        // [3][128*LDS_]
    float* Bgs = sm2 + 3 * 128 * LDS_;       // [3][64*LDS_]
    float* Bvs = Bgs + 3 * 64 * LDS_;        // [3][64*LDS_]

    int tid  = threadIdx.x;
    int bm   = blockIdx.y * 128;
    int bn   = blockIdx.x * 64;
    int c    = blockIdx.z;
    int warp = tid >> 5, lane = tid & 31;
    int wr = warp >> 1, wc = warp & 1;
    int wm = wr * 32,  wn = wc * 32;
    int g = lane >> 2, t = lane & 3;

    float accg[2][4][4], accv[2][4][4];
    #pragma unroll
    for (int i = 0; i < 2; i++)
        #pragma unroll
        for (int j = 0; j < 4; j++)
            #pragma unroll
            for (int k = 0; k < 4; k++) { accg[i][j][k] = 0.f; accv[i][j][k] = 0.f; }

    int lrow = tid >> 3;
    int lcol = (tid & 7) * 4;
    const float* wg0 = g_wg + (size_t)c * DH * DH;
    const float* wv0 = g_wv + (size_t)c * DH * DH;
    const int NK = DH / 32;   // 16

    #pragma unroll
    for (int s = 0; s < 2; s++) {
        int k0 = s * 32;
        float* dA = As  + s * 128 * LDS_;
        float* dG = Bgs + s * 64 * LDS_;
        float* dV = Bvs + s * 64 * LDS_;
        #pragma unroll
        for (int it = 0; it < 4; it++) {
            int r = lrow + it * 32;
            cp16(&dA[r * LDS_ + lcol], g_xn + ((size_t)(bm + r) * 4 + c) * DH + k0 + lcol);
        }
        #pragma unroll
        for (int it = 0; it < 2; it++) {
            int r = lrow + it * 32;
            cp16(&dG[r * LDS_ + lcol], wg0 + (size_t)(bn + r) * DH + k0 + lcol);
            cp16(&dV[r * LDS_ + lcol], wv0 + (size_t)(bn + r) * DH + k0 + lcol);
        }
        cp_commit();
    }

    int slot = 0, nslot = 2;
    for (int i = 0; i < NK; i++) {
        cp_wait1();
        __syncthreads();

        if (i + 2 < NK) {
            int k0 = (i + 2) * 32;
            float* dA = As  + nslot * 128 * LDS_;
            float* dG = Bgs + nslot * 64 * LDS_;
            float* dV = Bvs + nslot * 64 * LDS_;
            #pragma unroll
            for (int it = 0; it < 4; it++) {
                int r = lrow + it * 32;
                cp16(&dA[r * LDS_ + lcol], g_xn + ((size_t)(bm + r) * 4 + c) * DH + k0 + lcol);
            }
            #pragma unroll
            for (int it = 0; it < 2; it++) {
                int r = lrow + it * 32;
                cp16(&dG[r * LDS_ + lcol], wg0 + (size_t)(bn + r) * DH + k0 + lcol);
                cp16(&dV[r * LDS_ + lcol], wv0 + (size_t)(bn + r) * DH + k0 + lcol);
            }
        }
        cp_commit();

        const float* cAf = As  + slot * 128 * LDS_;
        const float* cGf = Bgs + slot * 64 * LDS_;
        const float* cVf = Bvs + slot * 64 * LDS_;
        float4 af[2][2], bgf[4], bvf[4];
        #pragma unroll
        for (int j = 0; j < 4; j++) {
            if ((j & 1) == 0) {
                int off = t * 8 + (j >> 1) * 4;
                #pragma unroll
                for (int mt = 0; mt < 2; mt++) {
                    int r0 = wm + mt * 16;
                    af[mt][0] = *(const float4*)&cAf[(r0 + g    ) * LDS_ + off];
                    af[mt][1] = *(const float4*)&cAf[(r0 + 8 + g) * LDS_ + off];
                }
                #pragma unroll
                for (int nt = 0; nt < 4; nt++) {
                    int n0 = wn + nt * 8;
                    bgf[nt] = *(const float4*)&cGf[(n0 + g) * LDS_ + off];
                    bvf[nt] = *(const float4*)&cVf[(n0 + g) * LDS_ + off];
                }
            }
            const int e = (j & 1) * 2;
            unsigned afr[2][4];
            #pragma unroll
            for (int mt = 0; mt < 2; mt++) {
                afr[mt][0] = __float_as_uint(F4C(af[mt][0], e));
                afr[mt][1] = __float_as_uint(F4C(af[mt][1], e));
                afr[mt][2] = __float_as_uint(F4C(af[mt][0], e + 1));
                afr[mt][3] = __float_as_uint(F4C(af[mt][1], e + 1));
            }
            #pragma unroll
            for (int nt = 0; nt < 4; nt++) {
                unsigned bg2[2] = { __float_as_uint(F4C(bgf[nt], e)),
                                    __float_as_uint(F4C(bgf[nt], e + 1)) };
                unsigned bv2[2] = { __float_as_uint(F4C(bvf[nt], e)),
                                    __float_as_uint(F4C(bvf[nt], e + 1)) };
                #pragma unroll
                for (int mt = 0; mt < 2; mt++) {
                    mma_tf32(accg[mt][nt], afr[mt], bg2);
                    mma_tf32(accv[mt][nt], afr[mt], bv2);
                }
            }
        }
        slot = (slot == 2) ? 0 : slot + 1;
        nslot = (nslot == 2) ? 0 : nslot + 1;
    }

    #pragma unroll
    for (int mt = 0; mt < 2; mt++) {
        #pragma unroll
        for (int nt = 0; nt < 4; nt++) {
            int row0 = bm + wm + mt * 16 + g;
            int col0 = bn + wn + nt * 8 + t * 2;
            int blk  = col0 & ~31;
            int p0   = blk + permk(col0 & 31);
            int p1   = blk + permk((col0 + 1) & 31);
            #pragma unroll
            for (int half = 0; half < 2; half++) {
                int rr = row0 + half * 8;
                float gte0 = accg[mt][nt][half * 2 + 0];
                float gte1 = accg[mt][nt][half * 2 + 1];
                float val0 = accv[mt][nt][half * 2 + 0];
                float val1 = accv[mt][nt][half * 2 + 1];
                float h0 = gte0 / (1.f + expf(-gte0)) * val0;
                float h1 = gte1 / (1.f + expf(-gte1)) * val1;
                float* dst = g_h + ((size_t)rr * 4 + c) * DH;
                dst[p0] = __uint_as_float(f2tf(h0));
                dst[p1] = __uint_as_float(f2tf(h1));
            }
        }
    }
}

// =====================================================================
// Stage 4: per-camera A[16384,36] = h_c @ w_out^T. Permuted operands,
// vectorized frags, 2-stage.
// =====================================================================
__global__ __launch_bounds__(256, 2) void gemm3_kernel()
{
    extern __shared__ float sm3[];
    float* As = sm3;
    float* Bs = sm3 + 2 * 128 * LDS_;

    int tid  = threadIdx.x;
    int bm   = blockIdx.y * 128;
    int c    = blockIdx.z;
    int warp = tid >> 5, lane = tid & 31;
    int wm   = warp * 16;
    int g = lane >> 2, t = lane & 3;

    for (int i = tid; i < 2 * 4 * LDS_; i += 256) {
        int b = i / (4 * LDS_);
        int rem = i % (4 * LDS_);
        Bs[b * 40 * LDS_ + 36 * LDS_ + rem] = 0.f;
    }

    float acc[5][4];
    #pragma unroll
    for (int j = 0; j < 5; j++)
        #pragma unroll
        for (int k = 0; k < 4; k++) acc[j][k] = 0.f;

    int lrow = tid >> 3;
    int lcol = (tid & 7) * 4;
    const float* wo0 = g_wo + (size_t)c * 36 * DH;
    const int NK = DH / 32;

    {
        #pragma unroll
        for (int it = 0; it < 4; it++) {
            int r = lrow + it * 32;
            cp16(&As[r * LDS_ + lcol], g_h + ((size_t)(bm + r) * 4 + c) * DH + lcol);
        }
        for (int i2 = tid; i2 < 288; i2 += 256) {
            int r = i2 >> 3, cc = (i2 & 7) * 4;
            cp16(&Bs[r * LDS_ + cc], wo0 + (size_t)r * DH + cc);
        }
        cp_commit();
    }

    for (int i = 0; i < NK; i++) {
        if (i + 1 < NK) {
            int k0 = (i + 1) * 32;
            int b = (i + 1) & 1;
            float* dA = As + b * 128 * LDS_;
            float* dB = Bs + b * 40 * LDS_;
            #pragma unroll
            for (int it = 0; it < 4; it++) {
                int r = lrow + it * 32;
                cp16(&dA[r * LDS_ + lcol], g_h + ((size_t)(bm + r) * 4 + c) * DH + k0 + lcol);
            }
            for (int i2 = tid; i2 < 288; i2 += 256) {
                int r = i2 >> 3, cc = (i2 & 7) * 4;
                cp16(&dB[r * LDS_ + cc], wo0 + (size_t)r * DH + k0 + cc);
            }
            cp_commit(); cp_wait1();
        } else {
            cp_wait0();
        }
        __syncthreads();

        int b = i & 1;
        const float* cAc = As + b * 128 * LDS_;
        const float* cBc = Bs + b * 40 * LDS_;
        float4 af2[2], bf[5];
        #pragma unroll
        for (int j = 0; j < 4; j++) {
            if ((j & 1) == 0) {
                int off = t * 8 + (j >> 1) * 4;
                af2[0] = *(const float4*)&cAc[(wm + g    ) * LDS_ + off];
                af2[1] = *(const float4*)&cAc[(wm + 8 + g) * LDS_ + off];
                #pragma unroll
                for (int nt = 0; nt < 5; nt++)
                    bf[nt] = *(const float4*)&cBc[(nt * 8 + g) * LDS_ + off];
            }
            const int e = (j & 1) * 2;
            unsigned afr[4];
            afr[0] = __float_as_uint(F4C(af2[0], e));
            afr[1] = __float_as_uint(F4C(af2[1], e));
            afr[2] = __float_as_uint(F4C(af2[0], e + 1));
            afr[3] = __float_as_uint(F4C(af2[1], e + 1));
            #pragma unroll
            for (int nt = 0; nt < 5; nt++) {
                unsigned b2[2] = { __float_as_uint(F4C(bf[nt], e)),
                                   __float_as_uint(F4C(bf[nt], e + 1)) };
                mma_tf32(acc[nt], afr, b2);
            }
        }
        __syncthreads();
    }

    #pragma unroll
    for (int nt = 0; nt < 5; nt++) {
        int col = nt * 8 + t * 2;
        if (col < 36) {
            int row0 = bm + wm + g;
            size_t base0 = ((size_t)row0 * 4 + c) * 36;
            size_t base1 = ((size_t)(row0 + 8) * 4 + c) * 36;
            g_A[base0 + col]     = acc[nt][0];
            g_A[base0 + col + 1] = acc[nt][1];
            g_A[base1 + col]     = acc[nt][2];
            g_A[base1 + col + 1] = acc[nt][3];
        }
    }
}

// =====================================================================
// Stage 5: skew + clip + expm (scale-square Taylor 12), out[C,B,6,6]
// =====================================================================
__global__ __launch_bounds__(128) void expm_kernel(float* __restrict__ out)
{
    int m = blockIdx.x * blockDim.x + threadIdx.x;
    if (m >= MTOT) return;
    int c = m & 3, b = m >> 2;

    const float* src = g_A + (size_t)m * 36;
    float raw[36];
    #pragma unroll
    for (int i = 0; i < 36; i++) raw[i] = src[i];

    float A[36]; float ss = 0.f;
    #pragma unroll
    for (int i = 0; i < 6; i++)
        #pragma unroll
        for (int j = 0; j < 6; j++) {
            float v = raw[i * 6 + j] - raw[j * 6 + i];
            A[i * 6 + j] = v; ss += v * v;
        }
    float frob  = sqrtf(ss);
    float scale = fminf(frob, 3.0f) / fmaxf(frob, 1e-8f);

    float As[36];
    #pragma unroll
    for (int i = 0; i < 36; i++) As[i] = A[i] * scale * 0.0625f;

    float E[36], term[36];
    #pragma unroll
    for (int i = 0; i < 36; i++) { E[i] = (i % 7 == 0) ? 1.f : 0.f; term[i] = E[i]; }

    #pragma unroll 1
    for (int k = 1; k <= 12; k++) {
        float nt[36];
        float inv = 1.f / (float)k;
        #pragma unroll
        for (int i = 0; i < 6; i++)
            #pragma unroll
            for (int j = 0; j < 6; j++) {
                float sacc = 0.f;
                #pragma unroll
                for (int l = 0; l < 6; l++) sacc += term[i * 6 + l] * As[l * 6 + j];
                nt[i * 6 + j] = sacc * inv;
            }
        #pragma unroll
        for (int i = 0; i < 36; i++) { term[i] = nt[i]; E[i] += nt[i]; }
    }
    #pragma unroll 1
    for (int s = 0; s < 4; s++) {
        float nt[36];
        #pragma unroll
        for (int i = 0; i < 6; i++)
            #pragma unroll
            for (int j = 0; j < 6; j++) {
                float sacc = 0.f;
                #pragma unroll
                for (int l = 0; l < 6; l++) sacc += E[i * 6 + l] * E[l * 6 + j];
                nt[i * 6 + j] = sacc;
            }
        #pragma unroll
        for (int i = 0; i < 36; i++) E[i] = nt[i];
    }

    float* dst = out + ((size_t)c * B_SZ + b) * 36;
    #pragma unroll
    for (int i = 0; i < 36; i++) dst[i] = E[i];
}

// =====================================================================
extern "C" void kernel_launch(void* const* d_in, const int* in_sizes, int n_in,
                              void* d_out, int out_size)
{
    const float* thumb  = (const float*)d_in[0];
    const float* proj_w = (const float*)d_in[1];
    const float* proj_b = (const float*)d_in[2];
    const float* gamma  = (const float*)d_in[3];
    const float* beta   = (const float*)d_in[4];
    const float* w_gate = (const float*)d_in[5];
    const float* w_val  = (const float*)d_in[6];
    const float* w_out  = (const float*)d_in[7];
    float* out = (float*)d_out;

    (void)in_sizes; (void)n_in; (void)out_size;

    const int SM1 = 3 * 2 * 128 * LDS_ * 4;                 // 110592
    const int SM2 = (3 * 128 * LDS_ + 6 * 64 * LDS_) * 4;   // 110592
    const int SM3 = (2 * 128 * LDS_ + 2 * 40 * LDS_) * 4;   // 48384

    cudaFuncSetAttribute(gemm1_kernel, cudaFuncAttributeMaxDynamicSharedMemorySize, SM1);
    cudaFuncSetAttribute(gemm2_kernel, cudaFuncAttributeMaxDynamicSharedMemorySize, SM2);
    cudaFuncSetAttribute(gemm3_kernel, cudaFuncAttributeMaxDynamicSharedMemorySize, SM3);

    round_weights<<<4384, 256>>>(proj_w, w_gate, w_val, w_out);
    gemm1_kernel<<<dim3(4, 512), 256, SM1>>>(thumb, proj_b);
    ln_kernel<<<MTOT / 8, 256>>>(gamma, beta);
    gemm2_kernel<<<dim3(8, 128, 4), 256, SM2>>>();
    gemm3_kernel<<<dim3(1, 128, 4), 256, SM3>>>();
    expm_kernel<<<MTOT / 128, 128>>>(out);
}

// round 7
// speedup vs baseline: 1.0560x; 1.0560x over previous
#include <cuda_runtime.h>
#include <math.h>
#include <stdint.h>

#define B_SZ   16384
#define C_CAM  4
#define DBB    2048
#define DH     512
#define MTOT   (B_SZ * C_CAM)

// -------- device-global scratch (no allocations allowed) --------
__device__ float g_reg[(size_t)MTOT * DH];
__device__ float g_xn [(size_t)MTOT * DH];
__device__ float g_h  [(size_t)MTOT * DH];
__device__ float g_A  [(size_t)MTOT * 36];
__device__ float g_pw [(size_t)DH * DBB];            // rna-rounded proj_w
__device__ float g_wg [(size_t)C_CAM * DH * DH];     // rna-rounded w_gate
__device__ float g_wv [(size_t)C_CAM * DH * DH];     // rna-rounded w_val
__device__ float g_wo [(size_t)C_CAM * 36 * DH];     // rna-rounded w_out

// -------- helpers --------
__device__ __forceinline__ unsigned f2tf(float x) {
    unsigned u; asm("cvt.rna.tf32.f32 %0, %1;" : "=r"(u) : "f"(x)); return u;
}
__device__ __forceinline__ void mma_tf32(float d[4], const unsigned a[4], const unsigned b[2]) {
    asm volatile(
        "mma.sync.aligned.m16n8k8.row.col.f32.tf32.tf32.f32 "
        "{%0,%1,%2,%3}, {%4,%5,%6,%7}, {%8,%9}, {%0,%1,%2,%3};\n"
        : "+f"(d[0]), "+f"(d[1]), "+f"(d[2]), "+f"(d[3])
        : "r"(a[0]), "r"(a[1]), "r"(a[2]), "r"(a[3]), "r"(b[0]), "r"(b[1]));
}
__device__ __forceinline__ void cp16(float* s, const float* g) {
    unsigned a = (unsigned)__cvta_generic_to_shared(s);
    asm volatile("cp.async.cg.shared.global [%0], [%1], 16;\n" :: "r"(a), "l"(g));
}
__device__ __forceinline__ void cp_commit() { asm volatile("cp.async.commit_group;\n" ::: "memory"); }
__device__ __forceinline__ void cp_wait1()  { asm volatile("cp.async.wait_group 1;\n" ::: "memory"); }
__device__ __forceinline__ void cp_wait0()  { asm volatile("cp.async.wait_group 0;\n" ::: "memory"); }

#define LDS_ 36   // 32 + 4 pad floats

// =====================================================================
// Stage 0: rna-round all weight matrices.
// =====================================================================
__global__ __launch_bounds__(256) void round_weights(
    const float* __restrict__ pw, const float* __restrict__ wg,
    const float* __restrict__ wv, const float* __restrict__ wo)
{
    int bi = blockIdx.x;
    if (bi < 4096) {
        int i = bi * 256 + threadIdx.x;
        g_pw[i] = __uint_as_float(f2tf(pw[i]));
        g_wg[i] = __uint_as_float(f2tf(wg[i]));
        g_wv[i] = __uint_as_float(f2tf(wv[i]));
    } else {
        int i = (bi - 4096) * 256 + threadIdx.x;
        g_wo[i] = __uint_as_float(f2tf(wo[i]));
    }
}

// =====================================================================
// Stage 1: reg[65536,512] = thumb[65536,2048] @ proj_w^T + bias
// BM=128, BN=128, BK=32, 3-stage cp.async, one barrier per tile.
// A raw fp32 (mma RZ-truncates); B pre-rounded. Scalar LDS frags.
// =====================================================================
__global__ __launch_bounds__(256, 2) void gemm1_kernel(
    const float* __restrict__ T, const float* __restrict__ bias)
{
    extern __shared__ float sm1[];
    float* As = sm1;                    // [3][128*LDS_]
    float* Bs = sm1 + 3 * 128 * LDS_;   // [3][128*LDS_]

    int tid  = threadIdx.x;
    int bm   = blockIdx.y * 128;
    int bn   = blockIdx.x * 128;
    int warp = tid >> 5, lane = tid & 31;
    int wr = warp >> 2, wc = warp & 3;
    int wm = wr * 64,  wn = wc * 32;
    int g = lane >> 2, t = lane & 3;

    float acc[4][4][4];
    #pragma unroll
    for (int i = 0; i < 4; i++)
        #pragma unroll
        for (int j = 0; j < 4; j++)
            #pragma unroll
            for (int k = 0; k < 4; k++) acc[i][j][k] = 0.f;

    int lrow = tid >> 3;
    int lcol = (tid & 7) * 4;
    const int NK = DBB / 32;        // 64

    #pragma unroll
    for (int s = 0; s < 2; s++) {
        float* dA = As + s * 128 * LDS_;
        float* dB = Bs + s * 128 * LDS_;
        int k0 = s * 32;
        #pragma unroll
        for (int it = 0; it < 4; it++) {
            int r = lrow + it * 32;
            cp16(&dA[r * LDS_ + lcol], T    + (size_t)(bm + r) * DBB + k0 + lcol);
            cp16(&dB[r * LDS_ + lcol], g_pw + (size_t)(bn + r) * DBB + k0 + lcol);
        }
        cp_commit();
    }

    int slot = 0, nslot = 2;
    for (int i = 0; i < NK; i++) {
        cp_wait1();
        __syncthreads();

        if (i + 2 < NK) {
            int k0 = (i + 2) * 32;
            float* dA = As + nslot * 128 * LDS_;
            float* dB = Bs + nslot * 128 * LDS_;
            #pragma unroll
            for (int it = 0; it < 4; it++) {
                int r = lrow + it * 32;
                cp16(&dA[r * LDS_ + lcol], T    + (size_t)(bm + r) * DBB + k0 + lcol);
                cp16(&dB[r * LDS_ + lcol], g_pw + (size_t)(bn + r) * DBB + k0 + lcol);
            }
        }
        cp_commit();

        const unsigned* cA = (const unsigned*)(As + slot * 128 * LDS_);
        const unsigned* cB = (const unsigned*)(Bs + slot * 128 * LDS_);
        #pragma unroll
        for (int kk = 0; kk < 32; kk += 8) {
            unsigned afr[4][4], bfr[4][2];
            #pragma unroll
            for (int mt = 0; mt < 4; mt++) {
                int r0 = wm + mt * 16;
                afr[mt][0] = cA[(r0 + g    ) * LDS_ + kk + t];
                afr[mt][1] = cA[(r0 + 8 + g) * LDS_ + kk + t];
                afr[mt][2] = cA[(r0 + g    ) * LDS_ + kk + t + 4];
                afr[mt][3] = cA[(r0 + 8 + g) * LDS_ + kk + t + 4];
            }
            #pragma unroll
            for (int nt = 0; nt < 4; nt++) {
                int n0 = wn + nt * 8;
                bfr[nt][0] = cB[(n0 + g) * LDS_ + kk + t];
                bfr[nt][1] = cB[(n0 + g) * LDS_ + kk + t + 4];
            }
            #pragma unroll
            for (int mt = 0; mt < 4; mt++)
                #pragma unroll
                for (int nt = 0; nt < 4; nt++)
                    mma_tf32(acc[mt][nt], afr[mt], bfr[nt]);
        }
        slot = (slot == 2) ? 0 : slot + 1;
        nslot = (nslot == 2) ? 0 : nslot + 1;
    }

    #pragma unroll
    for (int mt = 0; mt < 4; mt++) {
        #pragma unroll
        for (int nt = 0; nt < 4; nt++) {
            int row0 = bm + wm + mt * 16 + g;
            int col  = bn + wn + nt * 8 + t * 2;
            float b0 = bias[col], b1 = bias[col + 1];
            g_reg[(size_t)row0 * DH + col]           = acc[mt][nt][0] + b0;
            g_reg[(size_t)row0 * DH + col + 1]       = acc[mt][nt][1] + b1;
            g_reg[(size_t)(row0 + 8) * DH + col]     = acc[mt][nt][2] + b0;
            g_reg[(size_t)(row0 + 8) * DH + col + 1] = acc[mt][nt][3] + b1;
        }
    }
}

// =====================================================================
// Stage 2: LayerNorm (warp/row), rna-rounded output
// =====================================================================
__global__ __launch_bounds__(256) void ln_kernel(
    const float* __restrict__ gamma, const float* __restrict__ beta)
{
    int wglob = (blockIdx.x * blockDim.x + threadIdx.x) >> 5;
    int lane  = threadIdx.x & 31;
    if (wglob >= MTOT) return;
    int c = wglob & 3;
    const float* row = g_reg + (size_t)wglob * DH;
    float v[16], s = 0.f, s2 = 0.f;
    #pragma unroll
    for (int i = 0; i < 16; i++) {
        v[i] = row[lane + i * 32];
        s += v[i]; s2 += v[i] * v[i];
    }
    #pragma unroll
    for (int o = 16; o > 0; o >>= 1) {
        s  += __shfl_xor_sync(0xffffffffu, s,  o);
        s2 += __shfl_xor_sync(0xffffffffu, s2, o);
    }
    float mu   = s * (1.f / DH);
    float var  = s2 * (1.f / DH) - mu * mu;
    float rstd = rsqrtf(var + 1e-5f);
    float* orow = g_xn + (size_t)wglob * DH;
    const float* ga = gamma + c * DH;
    const float* be = beta  + c * DH;
    #pragma unroll
    for (int i = 0; i < 16; i++) {
        int k = lane + i * 32;
        float xn = (v[i] - mu) * rstd * ga[k] + be[k];
        orow[k] = __uint_as_float(f2tf(xn));
    }
}

// =====================================================================
// Stage 3: per-camera dual GEMM + SwiGLU. BM=128, BN=64, BK=32,
// 3-stage cp.async, one barrier per tile. Scalar LDS, no cvts.
// =====================================================================
__global__ __launch_bounds__(256, 2) void gemm2_kernel()
{
    extern __shared__ float sm2[];
    float* As  = sm2;                        // [3][128*LDS_]
    float* Bgs = sm2 + 3 * 128 * LDS_;       // [3][64*LDS_]
    float* Bvs = Bgs + 3 * 64 * LDS_;        // [3][64*LDS_]

    int tid  = threadIdx.x;
    int bm   = blockIdx.y * 128;
    int bn   = blockIdx.x * 64;
    int c    = blockIdx.z;
    int warp = tid >> 5, lane = tid & 31;
    int wr = warp >> 1, wc = warp & 1;
    int wm = wr * 32,  wn = wc * 32;
    int g = lane >> 2, t = lane & 3;

    float accg[2][4][4], accv[2][4][4];
    #pragma unroll
    for (int i = 0; i < 2; i++)
        #pragma unroll
        for (int j = 0; j < 4; j++)
            #pragma unroll
            for (int k = 0; k < 4; k++) { accg[i][j][k] = 0.f; accv[i][j][k] = 0.f; }

    int lrow = tid >> 3;
    int lcol = (tid & 7) * 4;
    const float* wg0 = g_wg + (size_t)c * DH * DH;
    const float* wv0 = g_wv + (size_t)c * DH * DH;
    const int NK = DH / 32;   // 16

    #pragma unroll
    for (int s = 0; s < 2; s++) {
        int k0 = s * 32;
        float* dA = As  + s * 128 * LDS_;
        float* dG = Bgs + s * 64 * LDS_;
        float* dV = Bvs + s * 64 * LDS_;
        #pragma unroll
        for (int it = 0; it < 4; it++) {
            int r = lrow + it * 32;
            cp16(&dA[r * LDS_ + lcol], g_xn + ((size_t)(bm + r) * 4 + c) * DH + k0 + lcol);
        }
        #pragma unroll
        for (int it = 0; it < 2; it++) {
            int r = lrow + it * 32;
            cp16(&dG[r * LDS_ + lcol], wg0 + (size_t)(bn + r) * DH + k0 + lcol);
            cp16(&dV[r * LDS_ + lcol], wv0 + (size_t)(bn + r) * DH + k0 + lcol);
        }
        cp_commit();
    }

    int slot = 0, nslot = 2;
    for (int i = 0; i < NK; i++) {
        cp_wait1();
        __syncthreads();

        if (i + 2 < NK) {
            int k0 = (i + 2) * 32;
            float* dA = As  + nslot * 128 * LDS_;
            float* dG = Bgs + nslot * 64 * LDS_;
            float* dV = Bvs + nslot * 64 * LDS_;
            #pragma unroll
            for (int it = 0; it < 4; it++) {
                int r = lrow + it * 32;
                cp16(&dA[r * LDS_ + lcol], g_xn + ((size_t)(bm + r) * 4 + c) * DH + k0 + lcol);
            }
            #pragma unroll
            for (int it = 0; it < 2; it++) {
                int r = lrow + it * 32;
                cp16(&dG[r * LDS_ + lcol], wg0 + (size_t)(bn + r) * DH + k0 + lcol);
                cp16(&dV[r * LDS_ + lcol], wv0 + (size_t)(bn + r) * DH + k0 + lcol);
            }
        }
        cp_commit();

        const unsigned* cA = (const unsigned*)(As  + slot * 128 * LDS_);
        const unsigned* cG = (const unsigned*)(Bgs + slot * 64 * LDS_);
        const unsigned* cV = (const unsigned*)(Bvs + slot * 64 * LDS_);
        #pragma unroll
        for (int kk = 0; kk < 32; kk += 8) {
            unsigned afr[2][4], bg[4][2], bv[4][2];
            #pragma unroll
            for (int mt = 0; mt < 2; mt++) {
                int r0 = wm + mt * 16;
                afr[mt][0] = cA[(r0 + g    ) * LDS_ + kk + t];
                afr[mt][1] = cA[(r0 + 8 + g) * LDS_ + kk + t];
                afr[mt][2] = cA[(r0 + g    ) * LDS_ + kk + t + 4];
                afr[mt][3] = cA[(r0 + 8 + g) * LDS_ + kk + t + 4];
            }
            #pragma unroll
            for (int nt = 0; nt < 4; nt++) {
                int n0 = wn + nt * 8;
                bg[nt][0] = cG[(n0 + g) * LDS_ + kk + t];
                bg[nt][1] = cG[(n0 + g) * LDS_ + kk + t + 4];
                bv[nt][0] = cV[(n0 + g) * LDS_ + kk + t];
                bv[nt][1] = cV[(n0 + g) * LDS_ + kk + t + 4];
            }
            #pragma unroll
            for (int mt = 0; mt < 2; mt++)
                #pragma unroll
                for (int nt = 0; nt < 4; nt++) {
                    mma_tf32(accg[mt][nt], afr[mt], bg[nt]);
                    mma_tf32(accv[mt][nt], afr[mt], bv[nt]);
                }
        }
        slot = (slot == 2) ? 0 : slot + 1;
        nslot = (nslot == 2) ? 0 : nslot + 1;
    }

    #pragma unroll
    for (int mt = 0; mt < 2; mt++) {
        #pragma unroll
        for (int nt = 0; nt < 4; nt++) {
            int row0 = bm + wm + mt * 16 + g;
            int col  = bn + wn + nt * 8 + t * 2;
            #pragma unroll
            for (int half = 0; half < 2; half++) {
                int rr = row0 + half * 8;
                float gte0 = accg[mt][nt][half * 2 + 0];
                float gte1 = accg[mt][nt][half * 2 + 1];
                float val0 = accv[mt][nt][half * 2 + 0];
                float val1 = accv[mt][nt][half * 2 + 1];
                float h0 = gte0 / (1.f + expf(-gte0)) * val0;
                float h1 = gte1 / (1.f + expf(-gte1)) * val1;
                float* dst = g_h + ((size_t)rr * 4 + c) * DH + col;
                dst[0] = __uint_as_float(f2tf(h0));
                dst[1] = __uint_as_float(f2tf(h1));
            }
        }
    }
}

// =====================================================================
// Stage 4: per-camera A[16384,36] = h_c @ w_out^T. 2-stage, scalar LDS.
// =====================================================================
__global__ __launch_bounds__(256, 2) void gemm3_kernel()
{
    extern __shared__ float sm3[];
    float* As = sm3;
    float* Bs = sm3 + 2 * 128 * LDS_;

    int tid  = threadIdx.x;
    int bm   = blockIdx.y * 128;
    int c    = blockIdx.z;
    int warp = tid >> 5, lane = tid & 31;
    int wm   = warp * 16;
    int g = lane >> 2, t = lane & 3;

    for (int i = tid; i < 2 * 4 * LDS_; i += 256) {
        int b = i / (4 * LDS_);
        int rem = i % (4 * LDS_);
        Bs[b * 40 * LDS_ + 36 * LDS_ + rem] = 0.f;
    }

    float acc[5][4];
    #pragma unroll
    for (int j = 0; j < 5; j++)
        #pragma unroll
        for (int k = 0; k < 4; k++) acc[j][k] = 0.f;

    int lrow = tid >> 3;
    int lcol = (tid & 7) * 4;
    const float* wo0 = g_wo + (size_t)c * 36 * DH;
    const int NK = DH / 32;

    {
        #pragma unroll
        for (int it = 0; it < 4; it++) {
            int r = lrow + it * 32;
            cp16(&As[r * LDS_ + lcol], g_h + ((size_t)(bm + r) * 4 + c) * DH + lcol);
        }
        for (int i2 = tid; i2 < 288; i2 += 256) {
            int r = i2 >> 3, cc = (i2 & 7) * 4;
            cp16(&Bs[r * LDS_ + cc], wo0 + (size_t)r * DH + cc);
        }
        cp_commit();
    }

    for (int i = 0; i < NK; i++) {
        if (i + 1 < NK) {
            int k0 = (i + 1) * 32;
            int b = (i + 1) & 1;
            float* dA = As + b * 128 * LDS_;
            float* dB = Bs + b * 40 * LDS_;
            #pragma unroll
            for (int it = 0; it < 4; it++) {
                int r = lrow + it * 32;
                cp16(&dA[r * LDS_ + lcol], g_h + ((size_t)(bm + r) * 4 + c) * DH + k0 + lcol);
            }
            for (int i2 = tid; i2 < 288; i2 += 256) {
                int r = i2 >> 3, cc = (i2 & 7) * 4;
                cp16(&dB[r * LDS_ + cc], wo0 + (size_t)r * DH + k0 + cc);
            }
            cp_commit(); cp_wait1();
        } else {
            cp_wait0();
        }
        __syncthreads();

        int b = i & 1;
        const unsigned* cAc = (const unsigned*)(As + b * 128 * LDS_);
        const unsigned* cBc = (const unsigned*)(Bs + b * 40 * LDS_);
        #pragma unroll
        for (int kk = 0; kk < 32; kk += 8) {
            unsigned afr[4], bfr[5][2];
            afr[0] = cAc[(wm + g    ) * LDS_ + kk + t];
            afr[1] = cAc[(wm + 8 + g) * LDS_ + kk + t];
            afr[2] = cAc[(wm + g    ) * LDS_ + kk + t + 4];
            afr[3] = cAc[(wm + 8 + g) * LDS_ + kk + t + 4];
            #pragma unroll
            for (int nt = 0; nt < 5; nt++) {
                int nn = nt * 8;
                bfr[nt][0] = cBc[(nn + g) * LDS_ + kk + t];
                bfr[nt][1] = cBc[(nn + g) * LDS_ + kk + t + 4];
            }
            #pragma unroll
            for (int nt = 0; nt < 5; nt++)
                mma_tf32(acc[nt], afr, bfr[nt]);
        }
        __syncthreads();
    }

    #pragma unroll
    for (int nt = 0; nt < 5; nt++) {
        int col = nt * 8 + t * 2;
        if (col < 36) {
            int row0 = bm + wm + g;
            size_t base0 = ((size_t)row0 * 4 + c) * 36;
            size_t base1 = ((size_t)(row0 + 8) * 4 + c) * 36;
            g_A[base0 + col]     = acc[nt][0];
            g_A[base0 + col + 1] = acc[nt][1];
            g_A[base1 + col]     = acc[nt][2];
            g_A[base1 + col + 1] = acc[nt][3];
        }
    }
}

// =====================================================================
// Stage 5: skew + clip + expm (scale-square Taylor 12), out[C,B,6,6]
// =====================================================================
__global__ __launch_bounds__(128) void expm_kernel(float* __restrict__ out)
{
    int m = blockIdx.x * blockDim.x + threadIdx.x;
    if (m >= MTOT) return;
    int c = m & 3, b = m >> 2;

    const float* src = g_A + (size_t)m * 36;
    float raw[36];
    #pragma unroll
    for (int i = 0; i < 36; i++) raw[i] = src[i];

    float A[36]; float ss = 0.f;
    #pragma unroll
    for (int i = 0; i < 6; i++)
        #pragma unroll
        for (int j = 0; j < 6; j++) {
            float v = raw[i * 6 + j] - raw[j * 6 + i];
            A[i * 6 + j] = v; ss += v * v;
        }
    float frob  = sqrtf(ss);
    float scale = fminf(frob, 3.0f) / fmaxf(frob, 1e-8f);

    float As[36];
    #pragma unroll
    for (int i = 0; i < 36; i++) As[i] = A[i] * scale * 0.0625f;

    float E[36], term[36];
    #pragma unroll
    for (int i = 0; i < 36; i++) { E[i] = (i % 7 == 0) ? 1.f : 0.f; term[i] = E[i]; }

    #pragma unroll 1
    for (int k = 1; k <= 12; k++) {
        float nt[36];
        float inv = 1.f / (float)k;
        #pragma unroll
        for (int i = 0; i < 6; i++)
            #pragma unroll
            for (int j = 0; j < 6; j++) {
                float sacc = 0.f;
                #pragma unroll
                for (int l = 0; l < 6; l++) sacc += term[i * 6 + l] * As[l * 6 + j];
                nt[i * 6 + j] = sacc * inv;
            }
        #pragma unroll
        for (int i = 0; i < 36; i++) { term[i] = nt[i]; E[i] += nt[i]; }
    }
    #pragma unroll 1
    for (int s = 0; s < 4; s++) {
        float nt[36];
        #pragma unroll
        for (int i = 0; i < 6; i++)
            #pragma unroll
            for (int j = 0; j < 6; j++) {
                float sacc = 0.f;
                #pragma unroll
                for (int l = 0; l < 6; l++) sacc += E[i * 6 + l] * E[l * 6 + j];
                nt[i * 6 + j] = sacc;
            }
        #pragma unroll
        for (int i = 0; i < 36; i++) E[i] = nt[i];
    }

    float* dst = out + ((size_t)c * B_SZ + b) * 36;
    #pragma unroll
    for (int i = 0; i < 36; i++) dst[i] = E[i];
}

// =====================================================================
extern "C" void kernel_launch(void* const* d_in, const int* in_sizes, int n_in,
                              void* d_out, int out_size)
{
    const float* thumb  = (const float*)d_in[0];
    const float* proj_w = (const float*)d_in[1];
    const float* proj_b = (const float*)d_in[2];
    const float* gamma  = (const float*)d_in[3];
    const float* beta   = (const float*)d_in[4];
    const float* w_gate = (const float*)d_in[5];
    const float* w_val  = (const float*)d_in[6];
    const float* w_out  = (const float*)d_in[7];
    float* out = (float*)d_out;

    (void)in_sizes; (void)n_in; (void)out_size;

    const int SM1 = 3 * 2 * 128 * LDS_ * 4;                 // 110592
    const int SM2 = (3 * 128 * LDS_ + 6 * 64 * LDS_) * 4;   // 110592
    const int SM3 = (2 * 128 * LDS_ + 2 * 40 * LDS_) * 4;   // 48384

    cudaFuncSetAttribute(gemm1_kernel, cudaFuncAttributeMaxDynamicSharedMemorySize, SM1);
    cudaFuncSetAttribute(gemm2_kernel, cudaFuncAttributeMaxDynamicSharedMemorySize, SM2);
    cudaFuncSetAttribute(gemm3_kernel, cudaFuncAttributeMaxDynamicSharedMemorySize, SM3);

    round_weights<<<4384, 256>>>(proj_w, w_gate, w_val, w_out);
    gemm1_kernel<<<dim3(4, 512), 256, SM1>>>(thumb, proj_b);
    ln_kernel<<<MTOT / 8, 256>>>(gamma, beta);
    gemm2_kernel<<<dim3(8, 128, 4), 256, SM2>>>();
    gemm3_kernel<<<dim3(1, 128, 4), 256, SM3>>>();
    expm_kernel<<<MTOT / 128, 128>>>(out);
}

// round 8
// speedup vs baseline: 1.6806x; 1.5915x over previous
#include <cuda_runtime.h>
#include <cuda_fp16.h>
#include <math.h>
#include <stdint.h>

#define B_SZ   16384
#define C_CAM  4
#define DBB    2048
#define DH     512
#define MTOT   (B_SZ * C_CAM)

// -------- device-global scratch (no allocations allowed) --------
__device__ float  g_reg[(size_t)MTOT * DH];
__device__ float  g_A  [(size_t)MTOT * 36];
__device__ __half g_t16 [(size_t)MTOT * DBB];          // fp16 thumbnails
__device__ __half g_xn16[(size_t)MTOT * DH];           // fp16 LN output
__device__ __half g_h16 [(size_t)MTOT * DH];           // fp16 swiglu output
__device__ __half g_pw16[(size_t)DH * DBB];
__device__ __half g_wg16[(size_t)C_CAM * DH * DH];
__device__ __half g_wv16[(size_t)C_CAM * DH * DH];
__device__ __half g_wo16[(size_t)C_CAM * 36 * DH];

// -------- helpers --------
__device__ __forceinline__ void mma_f16(float d[4], const unsigned a[4], const unsigned b[2]) {
    asm volatile(
        "mma.sync.aligned.m16n8k16.row.col.f32.f16.f16.f32 "
        "{%0,%1,%2,%3}, {%4,%5,%6,%7}, {%8,%9}, {%0,%1,%2,%3};\n"
        : "+f"(d[0]), "+f"(d[1]), "+f"(d[2]), "+f"(d[3])
        : "r"(a[0]), "r"(a[1]), "r"(a[2]), "r"(a[3]), "r"(b[0]), "r"(b[1]));
}
__device__ __forceinline__ void cp16(void* s, const void* g) {
    unsigned a = (unsigned)__cvta_generic_to_shared(s);
    asm volatile("cp.async.cg.shared.global [%0], [%1], 16;\n" :: "r"(a), "l"(g));
}
__device__ __forceinline__ void cp_commit() { asm volatile("cp.async.commit_group;\n" ::: "memory"); }
__device__ __forceinline__ void cp_wait1()  { asm volatile("cp.async.wait_group 1;\n" ::: "memory"); }
__device__ __forceinline__ void cp_wait0()  { asm volatile("cp.async.wait_group 0;\n" ::: "memory"); }

#define LDSU 36   // uints per smem row: 32 data (=64 halves) + 4 pad

// =====================================================================
// Stage -1: convert thumbnails fp32 -> fp16 (8 elems/thread)
// =====================================================================
__global__ __launch_bounds__(256) void conv_thumb(const float* __restrict__ T)
{
    size_t t = (size_t)blockIdx.x * 256 + threadIdx.x;
    const float4* s4 = (const float4*)T;
    float4 a = s4[2 * t], b = s4[2 * t + 1];
    __half2 h0 = __floats2half2_rn(a.x, a.y);
    __half2 h1 = __floats2half2_rn(a.z, a.w);
    __half2 h2 = __floats2half2_rn(b.x, b.y);
    __half2 h3 = __floats2half2_rn(b.z, b.w);
    uint4 o;
    o.x = *(unsigned*)&h0; o.y = *(unsigned*)&h1;
    o.z = *(unsigned*)&h2; o.w = *(unsigned*)&h3;
    ((uint4*)g_t16)[t] = o;
}

// =====================================================================
// Stage 0: convert weights fp32 -> fp16
// =====================================================================
__global__ __launch_bounds__(256) void round_weights(
    const float* __restrict__ pw, const float* __restrict__ wg,
    const float* __restrict__ wv, const float* __restrict__ wo)
{
    int bi = blockIdx.x;
    if (bi < 4096) {
        int i = bi * 256 + threadIdx.x;
        g_pw16[i] = __float2half_rn(pw[i]);
        g_wg16[i] = __float2half_rn(wg[i]);
        g_wv16[i] = __float2half_rn(wv[i]);
    } else {
        int i = (bi - 4096) * 256 + threadIdx.x;
        g_wo16[i] = __float2half_rn(wo[i]);
    }
}

// =====================================================================
// Stage 1: reg[65536,512] = t16[65536,2048] @ pw16^T + bias   (fp16 mma)
// BM=128, BN=128, BK=64 halves (32 uints). 3-stage, 1 barrier/tile. NK=32.
// =====================================================================
__global__ __launch_bounds__(256, 2) void gemm1_kernel(const float* __restrict__ bias)
{
    extern __shared__ __align__(16) unsigned smb1[];
    unsigned* As = smb1;                    // [3][128*LDSU]
    unsigned* Bs = smb1 + 3 * 128 * LDSU;   // [3][128*LDSU]

    int tid  = threadIdx.x;
    int bm   = blockIdx.y * 128;
    int bn   = blockIdx.x * 128;
    int warp = tid >> 5, lane = tid & 31;
    int wr = warp >> 2, wc = warp & 3;
    int wm = wr * 64,  wn = wc * 32;
    int g = lane >> 2, t = lane & 3;

    float acc[4][4][4];
    #pragma unroll
    for (int i = 0; i < 4; i++)
        #pragma unroll
        for (int j = 0; j < 4; j++)
            #pragma unroll
            for (int k = 0; k < 4; k++) acc[i][j][k] = 0.f;

    int lrow = tid >> 3;            // 0..31
    int lcu  = (tid & 7) * 4;       // uint offset in row
    int lch  = (tid & 7) * 8;       // half offset in gmem row
    const int NK = DBB / 64;        // 32

    #pragma unroll
    for (int s = 0; s < 2; s++) {
        unsigned* dA = As + s * 128 * LDSU;
        unsigned* dB = Bs + s * 128 * LDSU;
        int k0 = s * 64;
        #pragma unroll
        for (int it = 0; it < 4; it++) {
            int r = lrow + it * 32;
            cp16(&dA[r * LDSU + lcu], g_t16  + (size_t)(bm + r) * DBB + k0 + lch);
            cp16(&dB[r * LDSU + lcu], g_pw16 + (size_t)(bn + r) * DBB + k0 + lch);
        }
        cp_commit();
    }

    int slot = 0, nslot = 2;
    for (int i = 0; i < NK; i++) {
        cp_wait1();
        __syncthreads();

        if (i + 2 < NK) {
            int k0 = (i + 2) * 64;
            unsigned* dA = As + nslot * 128 * LDSU;
            unsigned* dB = Bs + nslot * 128 * LDSU;
            #pragma unroll
            for (int it = 0; it < 4; it++) {
                int r = lrow + it * 32;
                cp16(&dA[r * LDSU + lcu], g_t16  + (size_t)(bm + r) * DBB + k0 + lch);
                cp16(&dB[r * LDSU + lcu], g_pw16 + (size_t)(bn + r) * DBB + k0 + lch);
            }
        }
        cp_commit();

        const unsigned* cA = As + slot * 128 * LDSU;
        const unsigned* cB = Bs + slot * 128 * LDSU;
        #pragma unroll
        for (int kk = 0; kk < 32; kk += 8) {     // kk = uint col base; covers k16 halves
            unsigned afr[4][4], bfr[4][2];
            #pragma unroll
            for (int mt = 0; mt < 4; mt++) {
                int r0 = wm + mt * 16;
                afr[mt][0] = cA[(r0 + g    ) * LDSU + kk + t];
                afr[mt][1] = cA[(r0 + 8 + g) * LDSU + kk + t];
                afr[mt][2] = cA[(r0 + g    ) * LDSU + kk + t + 4];
                afr[mt][3] = cA[(r0 + 8 + g) * LDSU + kk + t + 4];
            }
            #pragma unroll
            for (int nt = 0; nt < 4; nt++) {
                int n0 = wn + nt * 8;
                bfr[nt][0] = cB[(n0 + g) * LDSU + kk + t];
                bfr[nt][1] = cB[(n0 + g) * LDSU + kk + t + 4];
            }
            #pragma unroll
            for (int mt = 0; mt < 4; mt++)
                #pragma unroll
                for (int nt = 0; nt < 4; nt++)
                    mma_f16(acc[mt][nt], afr[mt], bfr[nt]);
        }
        slot = (slot == 2) ? 0 : slot + 1;
        nslot = (nslot == 2) ? 0 : nslot + 1;
    }

    #pragma unroll
    for (int mt = 0; mt < 4; mt++) {
        #pragma unroll
        for (int nt = 0; nt < 4; nt++) {
            int row0 = bm + wm + mt * 16 + g;
            int col  = bn + wn + nt * 8 + t * 2;
            float b0 = bias[col], b1 = bias[col + 1];
            g_reg[(size_t)row0 * DH + col]           = acc[mt][nt][0] + b0;
            g_reg[(size_t)row0 * DH + col + 1]       = acc[mt][nt][1] + b1;
            g_reg[(size_t)(row0 + 8) * DH + col]     = acc[mt][nt][2] + b0;
            g_reg[(size_t)(row0 + 8) * DH + col + 1] = acc[mt][nt][3] + b1;
        }
    }
}

// =====================================================================
// Stage 2: LayerNorm (warp/row), fp16 output (half2 stores)
// =====================================================================
__global__ __launch_bounds__(256) void ln_kernel(
    const float* __restrict__ gamma, const float* __restrict__ beta)
{
    int wglob = (blockIdx.x * blockDim.x + threadIdx.x) >> 5;
    int lane  = threadIdx.x & 31;
    if (wglob >= MTOT) return;
    int c = wglob & 3;
    const float2* row2 = (const float2*)(g_reg + (size_t)wglob * DH);
    float2 v[8]; float s = 0.f, s2 = 0.f;
    #pragma unroll
    for (int i = 0; i < 8; i++) {
        v[i] = row2[lane + i * 32];
        s += v[i].x + v[i].y;
        s2 += v[i].x * v[i].x + v[i].y * v[i].y;
    }
    #pragma unroll
    for (int o = 16; o > 0; o >>= 1) {
        s  += __shfl_xor_sync(0xffffffffu, s,  o);
        s2 += __shfl_xor_sync(0xffffffffu, s2, o);
    }
    float mu   = s * (1.f / DH);
    float var  = s2 * (1.f / DH) - mu * mu;
    float rstd = rsqrtf(var + 1e-5f);
    __half2* orow = (__half2*)(g_xn16 + (size_t)wglob * DH);
    const float2* ga2 = (const float2*)(gamma + c * DH);
    const float2* be2 = (const float2*)(beta  + c * DH);
    #pragma unroll
    for (int i = 0; i < 8; i++) {
        int idx = lane + i * 32;
        float2 ga = ga2[idx], be = be2[idx];
        float x0 = (v[i].x - mu) * rstd * ga.x + be.x;
        float x1 = (v[i].y - mu) * rstd * ga.y + be.y;
        orow[idx] = __floats2half2_rn(x0, x1);
    }
}

// =====================================================================
// Stage 3: per-camera dual GEMM + SwiGLU (fp16 mma). BM=128, BN=64,
// BK=64 halves. 3-stage, 1 barrier/tile. NK=8.
// =====================================================================
__global__ __launch_bounds__(256, 2) void gemm2_kernel()
{
    extern __shared__ __align__(16) unsigned smb2[];
    unsigned* As  = smb2;                       // [3][128*LDSU]
    unsigned* Bgs = smb2 + 3 * 128 * LDSU;      // [3][64*LDSU]
    unsigned* Bvs = Bgs + 3 * 64 * LDSU;        // [3][64*LDSU]

    int tid  = threadIdx.x;
    int bm   = blockIdx.y * 128;
    int bn   = blockIdx.x * 64;
    int c    = blockIdx.z;
    int warp = tid >> 5, lane = tid & 31;
    int wr = warp >> 1, wc = warp & 1;
    int wm = wr * 32,  wn = wc * 32;
    int g = lane >> 2, t = lane & 3;

    float accg[2][4][4], accv[2][4][4];
    #pragma unroll
    for (int i = 0; i < 2; i++)
        #pragma unroll
        for (int j = 0; j < 4; j++)
            #pragma unroll
            for (int k = 0; k < 4; k++) { accg[i][j][k] = 0.f; accv[i][j][k] = 0.f; }

    int lrow = tid >> 3;
    int lcu  = (tid & 7) * 4;
    int lch  = (tid & 7) * 8;
    const __half* wg0 = g_wg16 + (size_t)c * DH * DH;
    const __half* wv0 = g_wv16 + (size_t)c * DH * DH;
    const int NK = DH / 64;   // 8

    #pragma unroll
    for (int s = 0; s < 2; s++) {
        int k0 = s * 64;
        unsigned* dA = As  + s * 128 * LDSU;
        unsigned* dG = Bgs + s * 64 * LDSU;
        unsigned* dV = Bvs + s * 64 * LDSU;
        #pragma unroll
        for (int it = 0; it < 4; it++) {
            int r = lrow + it * 32;
            cp16(&dA[r * LDSU + lcu], g_xn16 + ((size_t)(bm + r) * 4 + c) * DH + k0 + lch);
        }
        #pragma unroll
        for (int it = 0; it < 2; it++) {
            int r = lrow + it * 32;
            cp16(&dG[r * LDSU + lcu], wg0 + (size_t)(bn + r) * DH + k0 + lch);
            cp16(&dV[r * LDSU + lcu], wv0 + (size_t)(bn + r) * DH + k0 + lch);
        }
        cp_commit();
    }

    int slot = 0, nslot = 2;
    for (int i = 0; i < NK; i++) {
        cp_wait1();
        __syncthreads();

        if (i + 2 < NK) {
            int k0 = (i + 2) * 64;
            unsigned* dA = As  + nslot * 128 * LDSU;
            unsigned* dG = Bgs + nslot * 64 * LDSU;
            unsigned* dV = Bvs + nslot * 64 * LDSU;
            #pragma unroll
            for (int it = 0; it < 4; it++) {
                int r = lrow + it * 32;
                cp16(&dA[r * LDSU + lcu], g_xn16 + ((size_t)(bm + r) * 4 + c) * DH + k0 + lch);
            }
            #pragma unroll
            for (int it = 0; it < 2; it++) {
                int r = lrow + it * 32;
                cp16(&dG[r * LDSU + lcu], wg0 + (size_t)(bn + r) * DH + k0 + lch);
                cp16(&dV[r * LDSU + lcu], wv0 + (size_t)(bn + r) * DH + k0 + lch);
            }
        }
        cp_commit();

        const unsigned* cA = As  + slot * 128 * LDSU;
        const unsigned* cG = Bgs + slot * 64 * LDSU;
        const unsigned* cV = Bvs + slot * 64 * LDSU;
        #pragma unroll
        for (int kk = 0; kk < 32; kk += 8) {
            unsigned afr[2][4], bg[4][2], bv[4][2];
            #pragma unroll
            for (int mt = 0; mt < 2; mt++) {
                int r0 = wm + mt * 16;
                afr[mt][0] = cA[(r0 + g    ) * LDSU + kk + t];
                afr[mt][1] = cA[(r0 + 8 + g) * LDSU + kk + t];
                afr[mt][2] = cA[(r0 + g    ) * LDSU + kk + t + 4];
                afr[mt][3] = cA[(r0 + 8 + g) * LDSU + kk + t + 4];
            }
            #pragma unroll
            for (int nt = 0; nt < 4; nt++) {
                int n0 = wn + nt * 8;
                bg[nt][0] = cG[(n0 + g) * LDSU + kk + t];
                bg[nt][1] = cG[(n0 + g) * LDSU + kk + t + 4];
                bv[nt][0] = cV[(n0 + g) * LDSU + kk + t];
                bv[nt][1] = cV[(n0 + g) * LDSU + kk + t + 4];
            }
            #pragma unroll
            for (int mt = 0; mt < 2; mt++)
                #pragma unroll
                for (int nt = 0; nt < 4; nt++) {
                    mma_f16(accg[mt][nt], afr[mt], bg[nt]);
                    mma_f16(accv[mt][nt], afr[mt], bv[nt]);
                }
        }
        slot = (slot == 2) ? 0 : slot + 1;
        nslot = (nslot == 2) ? 0 : nslot + 1;
    }

    #pragma unroll
    for (int mt = 0; mt < 2; mt++) {
        #pragma unroll
        for (int nt = 0; nt < 4; nt++) {
            int row0 = bm + wm + mt * 16 + g;
            int col  = bn + wn + nt * 8 + t * 2;
            #pragma unroll
            for (int half = 0; half < 2; half++) {
                int rr = row0 + half * 8;
                float gte0 = accg[mt][nt][half * 2 + 0];
                float gte1 = accg[mt][nt][half * 2 + 1];
                float val0 = accv[mt][nt][half * 2 + 0];
                float val1 = accv[mt][nt][half * 2 + 1];
                float h0 = gte0 / (1.f + expf(-gte0)) * val0;
                float h1 = gte1 / (1.f + expf(-gte1)) * val1;
                __half2* dst = (__half2*)(g_h16 + ((size_t)rr * 4 + c) * DH + col);
                *dst = __floats2half2_rn(h0, h1);
            }
        }
    }
}

// =====================================================================
// Stage 4: per-camera A[16384,36] = h16 @ wo16^T. BK=64 halves, 2-stage.
// =====================================================================
__global__ __launch_bounds__(256, 2) void gemm3_kernel()
{
    extern __shared__ __align__(16) unsigned smb3[];
    unsigned* As = smb3;                     // [2][128*LDSU]
    unsigned* Bs = smb3 + 2 * 128 * LDSU;    // [2][40*LDSU]

    int tid  = threadIdx.x;
    int bm   = blockIdx.y * 128;
    int c    = blockIdx.z;
    int warp = tid >> 5, lane = tid & 31;
    int wm   = warp * 16;
    int g = lane >> 2, t = lane & 3;

    // zero pad rows 36..39 of both B buffers
    for (int i = tid; i < 2 * 4 * LDSU; i += 256) {
        int b = i / (4 * LDSU);
        int rem = i % (4 * LDSU);
        Bs[b * 40 * LDSU + 36 * LDSU + rem] = 0u;
    }

    float acc[5][4];
    #pragma unroll
    for (int j = 0; j < 5; j++)
        #pragma unroll
        for (int k = 0; k < 4; k++) acc[j][k] = 0.f;

    int lrow = tid >> 3;
    int lcu  = (tid & 7) * 4;
    int lch  = (tid & 7) * 8;
    const __half* wo0 = g_wo16 + (size_t)c * 36 * DH;
    const int NK = DH / 64;   // 8

    {
        #pragma unroll
        for (int it = 0; it < 4; it++) {
            int r = lrow + it * 32;
            cp16(&As[r * LDSU + lcu], g_h16 + ((size_t)(bm + r) * 4 + c) * DH + lch);
        }
        for (int i2 = tid; i2 < 288; i2 += 256) {
            int r = i2 >> 3, cu = (i2 & 7) * 4;
            cp16(&Bs[r * LDSU + cu], wo0 + (size_t)r * DH + (i2 & 7) * 8);
        }
        cp_commit();
    }

    for (int i = 0; i < NK; i++) {
        if (i + 1 < NK) {
            int k0 = (i + 1) * 64;
            int b = (i + 1) & 1;
            unsigned* dA = As + b * 128 * LDSU;
            unsigned* dB = Bs + b * 40 * LDSU;
            #pragma unroll
            for (int it = 0; it < 4; it++) {
                int r = lrow + it * 32;
                cp16(&dA[r * LDSU + lcu], g_h16 + ((size_t)(bm + r) * 4 + c) * DH + k0 + lch);
            }
            for (int i2 = tid; i2 < 288; i2 += 256) {
                int r = i2 >> 3, cu = (i2 & 7) * 4;
                cp16(&dB[r * LDSU + cu], wo0 + (size_t)r * DH + k0 + (i2 & 7) * 8);
            }
            cp_commit(); cp_wait1();
        } else {
            cp_wait0();
        }
        __syncthreads();

        int b = i & 1;
        const unsigned* cAc = As + b * 128 * LDSU;
        const unsigned* cBc = Bs + b * 40 * LDSU;
        #pragma unroll
        for (int kk = 0; kk < 32; kk += 8) {
            unsigned afr[4], bfr[5][2];
            afr[0] = cAc[(wm + g    ) * LDSU + kk + t];
            afr[1] = cAc[(wm + 8 + g) * LDSU + kk + t];
            afr[2] = cAc[(wm + g    ) * LDSU + kk + t + 4];
            afr[3] = cAc[(wm + 8 + g) * LDSU + kk + t + 4];
            #pragma unroll
            for (int nt = 0; nt < 5; nt++) {
                int nn = nt * 8;
                bfr[nt][0] = cBc[(nn + g) * LDSU + kk + t];
                bfr[nt][1] = cBc[(nn + g) * LDSU + kk + t + 4];
            }
            #pragma unroll
            for (int nt = 0; nt < 5; nt++)
                mma_f16(acc[nt], afr, bfr[nt]);
        }
        __syncthreads();
    }

    #pragma unroll
    for (int nt = 0; nt < 5; nt++) {
        int col = nt * 8 + t * 2;
        if (col < 36) {
            int row0 = bm + wm + g;
            size_t base0 = ((size_t)row0 * 4 + c) * 36;
            size_t base1 = ((size_t)(row0 + 8) * 4 + c) * 36;
            g_A[base0 + col]     = acc[nt][0];
            g_A[base0 + col + 1] = acc[nt][1];
            g_A[base1 + col]     = acc[nt][2];
            g_A[base1 + col + 1] = acc[nt][3];
        }
    }
}

// =====================================================================
// Stage 5: skew + clip + expm (scale-square Taylor 12), out[C,B,6,6]
// =====================================================================
__global__ __launch_bounds__(128) void expm_kernel(float* __restrict__ out)
{
    int m = blockIdx.x * blockDim.x + threadIdx.x;
    if (m >= MTOT) return;
    int c = m & 3, b = m >> 2;

    const float* src = g_A + (size_t)m * 36;
    float raw[36];
    #pragma unroll
    for (int i = 0; i < 36; i++) raw[i] = src[i];

    float A[36]; float ss = 0.f;
    #pragma unroll
    for (int i = 0; i < 6; i++)
        #pragma unroll
        for (int j = 0; j < 6; j++) {
            float v = raw[i * 6 + j] - raw[j * 6 + i];
            A[i * 6 + j] = v; ss += v * v;
        }
    float frob  = sqrtf(ss);
    float scale = fminf(frob, 3.0f) / fmaxf(frob, 1e-8f);

    float As[36];
    #pragma unroll
    for (int i = 0; i < 36; i++) As[i] = A[i] * scale * 0.0625f;

    float E[36], term[36];
    #pragma unroll
    for (int i = 0; i < 36; i++) { E[i] = (i % 7 == 0) ? 1.f : 0.f; term[i] = E[i]; }

    #pragma unroll 1
    for (int k = 1; k <= 12; k++) {
        float nt[36];
        float inv = 1.f / (float)k;
        #pragma unroll
        for (int i = 0; i < 6; i++)
            #pragma unroll
            for (int j = 0; j < 6; j++) {
                float sacc = 0.f;
                #pragma unroll
                for (int l = 0; l < 6; l++) sacc += term[i * 6 + l] * As[l * 6 + j];
                nt[i * 6 + j] = sacc * inv;
            }
        #pragma unroll
        for (int i = 0; i < 36; i++) { term[i] = nt[i]; E[i] += nt[i]; }
    }
    #pragma unroll 1
    for (int s = 0; s < 4; s++) {
        float nt[36];
        #pragma unroll
        for (int i = 0; i < 6; i++)
            #pragma unroll
            for (int j = 0; j < 6; j++) {
                float sacc = 0.f;
                #pragma unroll
                for (int l = 0; l < 6; l++) sacc += E[i * 6 + l] * E[l * 6 + j];
                nt[i * 6 + j] = sacc;
            }
        #pragma unroll
        for (int i = 0; i < 36; i++) E[i] = nt[i];
    }

    float* dst = out + ((size_t)c * B_SZ + b) * 36;
    #pragma unroll
    for (int i = 0; i < 36; i++) dst[i] = E[i];
}

// =====================================================================
extern "C" void kernel_launch(void* const* d_in, const int* in_sizes, int n_in,
                              void* d_out, int out_size)
{
    const float* thumb  = (const float*)d_in[0];
    const float* proj_w = (const float*)d_in[1];
    const float* proj_b = (const float*)d_in[2];
    const float* gamma  = (const float*)d_in[3];
    const float* beta   = (const float*)d_in[4];
    const float* w_gate = (const float*)d_in[5];
    const float* w_val  = (const float*)d_in[6];
    const float* w_out  = (const float*)d_in[7];
    float* out = (float*)d_out;

    (void)in_sizes; (void)n_in; (void)out_size;

    const int SM1 = 3 * 2 * 128 * LDSU * 4;                 // 110592
    const int SM2 = (3 * 128 * LDSU + 6 * 64 * LDSU) * 4;   // 110592
    const int SM3 = (2 * 128 * LDSU + 2 * 40 * LDSU) * 4;   // 48384

    cudaFuncSetAttribute(gemm1_kernel, cudaFuncAttributeMaxDynamicSharedMemorySize, SM1);
    cudaFuncSetAttribute(gemm2_kernel, cudaFuncAttributeMaxDynamicSharedMemorySize, SM2);
    cudaFuncSetAttribute(gemm3_kernel, cudaFuncAttributeMaxDynamicSharedMemorySize, SM3);

    conv_thumb<<<65536, 256>>>(thumb);
    round_weights<<<4384, 256>>>(proj_w, w_gate, w_val, w_out);
    gemm1_kernel<<<dim3(4, 512), 256, SM1>>>(proj_b);
    ln_kernel<<<MTOT / 8, 256>>>(gamma, beta);
    gemm2_kernel<<<dim3(8, 128, 4), 256, SM2>>>();
    gemm3_kernel<<<dim3(1, 128, 4), 256, SM3>>>();
    expm_kernel<<<MTOT / 128, 128>>>(out);
}

// round 9
// speedup vs baseline: 1.8125x; 1.0785x over previous
#include <cuda_runtime.h>
#include <cuda_fp16.h>
#include <math.h>
#include <stdint.h>

#define B_SZ   16384
#define C_CAM  4
#define DBB    2048
#define DH     512
#define MTOT   (B_SZ * C_CAM)

// -------- device-global scratch (no allocations allowed) --------
__device__ float  g_reg[(size_t)MTOT * DH];
__device__ float  g_A  [(size_t)MTOT * 36];
__device__ __half g_t16 [(size_t)MTOT * DBB];
__device__ __half g_xn16[(size_t)MTOT * DH];
__device__ __half g_h16 [(size_t)MTOT * DH];
__device__ __half g_pw16[(size_t)DH * DBB];
__device__ __half g_wg16[(size_t)C_CAM * DH * DH];
__device__ __half g_wv16[(size_t)C_CAM * DH * DH];
__device__ __half g_wo16[(size_t)C_CAM * 36 * DH];

// -------- helpers --------
__device__ __forceinline__ void mma_f16(float d[4], const unsigned a[4], const unsigned b[2]) {
    asm volatile(
        "mma.sync.aligned.m16n8k16.row.col.f32.f16.f16.f32 "
        "{%0,%1,%2,%3}, {%4,%5,%6,%7}, {%8,%9}, {%0,%1,%2,%3};\n"
        : "+f"(d[0]), "+f"(d[1]), "+f"(d[2]), "+f"(d[3])
        : "r"(a[0]), "r"(a[1]), "r"(a[2]), "r"(a[3]), "r"(b[0]), "r"(b[1]));
}
__device__ __forceinline__ void ldsm4(unsigned r[4], unsigned saddr) {
    asm volatile("ldmatrix.sync.aligned.m8n8.x4.shared.b16 {%0,%1,%2,%3}, [%4];"
        : "=r"(r[0]), "=r"(r[1]), "=r"(r[2]), "=r"(r[3]) : "r"(saddr));
}
__device__ __forceinline__ void ldsm2(unsigned r[2], unsigned saddr) {
    asm volatile("ldmatrix.sync.aligned.m8n8.x2.shared.b16 {%0,%1}, [%2];"
        : "=r"(r[0]), "=r"(r[1]) : "r"(saddr));
}
__device__ __forceinline__ void cp16(void* s, const void* g) {
    unsigned a = (unsigned)__cvta_generic_to_shared(s);
    asm volatile("cp.async.cg.shared.global [%0], [%1], 16;\n" :: "r"(a), "l"(g));
}
__device__ __forceinline__ void cp_commit() { asm volatile("cp.async.commit_group;\n" ::: "memory"); }
__device__ __forceinline__ void cp_wait1()  { asm volatile("cp.async.wait_group 1;\n" ::: "memory"); }
__device__ __forceinline__ void cp_wait0()  { asm volatile("cp.async.wait_group 0;\n" ::: "memory"); }

#define LDSU 36   // uints per smem row: 32 data (=64 halves) + 4 pad

// lane-address offsets (uint units) for ldmatrix fragments
#define A_LANE_OFF(lane) (((lane) & 15) * LDSU + (((lane) >> 4) << 2))
#define B_LANE_OFF(lane) ((((lane) & 7) + (((lane) >> 4) << 3)) * LDSU + ((((lane) >> 3) & 1) << 2))
#define B2_LANE_OFF(lane) (((lane) & 7) * LDSU + ((((lane) >> 3) & 1) << 2))

// =====================================================================
// Stage -1: thumbnails fp32 -> fp16
// =====================================================================
__global__ __launch_bounds__(256) void conv_thumb(const float* __restrict__ T)
{
    size_t t = (size_t)blockIdx.x * 256 + threadIdx.x;
    const float4* s4 = (const float4*)T;
    float4 a = s4[2 * t], b = s4[2 * t + 1];
    __half2 h0 = __floats2half2_rn(a.x, a.y);
    __half2 h1 = __floats2half2_rn(a.z, a.w);
    __half2 h2 = __floats2half2_rn(b.x, b.y);
    __half2 h3 = __floats2half2_rn(b.z, b.w);
    uint4 o;
    o.x = *(unsigned*)&h0; o.y = *(unsigned*)&h1;
    o.z = *(unsigned*)&h2; o.w = *(unsigned*)&h3;
    ((uint4*)g_t16)[t] = o;
}

// =====================================================================
// Stage 0: weights fp32 -> fp16
// =====================================================================
__global__ __launch_bounds__(256) void round_weights(
    const float* __restrict__ pw, const float* __restrict__ wg,
    const float* __restrict__ wv, const float* __restrict__ wo)
{
    int bi = blockIdx.x;
    if (bi < 4096) {
        int i = bi * 256 + threadIdx.x;
        g_pw16[i] = __float2half_rn(pw[i]);
        g_wg16[i] = __float2half_rn(wg[i]);
        g_wv16[i] = __float2half_rn(wv[i]);
    } else {
        int i = (bi - 4096) * 256 + threadIdx.x;
        g_wo16[i] = __float2half_rn(wo[i]);
    }
}

// =====================================================================
// Stage 1: reg = t16 @ pw16^T + bias.  BM=128, BN=128, BK=64h.
// 3-stage cp.async, 1 barrier/tile, ldmatrix fragment loads. NK=32.
// =====================================================================
__global__ __launch_bounds__(256, 2) void gemm1_kernel(const float* __restrict__ bias)
{
    extern __shared__ __align__(16) unsigned smb1[];
    unsigned* As = smb1;                    // [3][128*LDSU]
    unsigned* Bs = smb1 + 3 * 128 * LDSU;   // [3][128*LDSU]

    int tid  = threadIdx.x;
    int bm   = blockIdx.y * 128;
    int bn   = blockIdx.x * 128;
    int warp = tid >> 5, lane = tid & 31;
    int wr = warp >> 2, wc = warp & 3;
    int wm = wr * 64,  wn = wc * 32;
    int g = lane >> 2, t = lane & 3;

    float acc[4][4][4];
    #pragma unroll
    for (int i = 0; i < 4; i++)
        #pragma unroll
        for (int j = 0; j < 4; j++)
            #pragma unroll
            for (int k = 0; k < 4; k++) acc[i][j][k] = 0.f;

    int lrow = tid >> 3;
    int lcu  = (tid & 7) * 4;
    int lch  = (tid & 7) * 8;
    const int NK = DBB / 64;        // 32

    const unsigned sAs = (unsigned)__cvta_generic_to_shared(As);
    const unsigned sBs = (unsigned)__cvta_generic_to_shared(Bs);
    const unsigned aLane = sAs + 4u * (unsigned)(wm * LDSU + A_LANE_OFF(lane));
    const unsigned bLane = sBs + 4u * (unsigned)(wn * LDSU + B_LANE_OFF(lane));

    #pragma unroll
    for (int s = 0; s < 2; s++) {
        unsigned* dA = As + s * 128 * LDSU;
        unsigned* dB = Bs + s * 128 * LDSU;
        int k0 = s * 64;
        #pragma unroll
        for (int it = 0; it < 4; it++) {
            int r = lrow + it * 32;
            cp16(&dA[r * LDSU + lcu], g_t16  + (size_t)(bm + r) * DBB + k0 + lch);
            cp16(&dB[r * LDSU + lcu], g_pw16 + (size_t)(bn + r) * DBB + k0 + lch);
        }
        cp_commit();
    }

    int slot = 0, nslot = 2;
    for (int i = 0; i < NK; i++) {
        cp_wait1();
        __syncthreads();

        if (i + 2 < NK) {
            int k0 = (i + 2) * 64;
            unsigned* dA = As + nslot * 128 * LDSU;
            unsigned* dB = Bs + nslot * 128 * LDSU;
            #pragma unroll
            for (int it = 0; it < 4; it++) {
                int r = lrow + it * 32;
                cp16(&dA[r * LDSU + lcu], g_t16  + (size_t)(bm + r) * DBB + k0 + lch);
                cp16(&dB[r * LDSU + lcu], g_pw16 + (size_t)(bn + r) * DBB + k0 + lch);
            }
        }
        cp_commit();

        unsigned aBase = aLane + 4u * (unsigned)(slot * 128 * LDSU);
        unsigned bBase = bLane + 4u * (unsigned)(slot * 128 * LDSU);
        #pragma unroll
        for (int kk = 0; kk < 32; kk += 8) {
            unsigned afr[4][4], b4[2][4];
            #pragma unroll
            for (int mt = 0; mt < 4; mt++)
                ldsm4(afr[mt], aBase + 4u * (unsigned)(mt * 16 * LDSU + kk));
            #pragma unroll
            for (int p = 0; p < 2; p++)
                ldsm4(b4[p], bBase + 4u * (unsigned)(p * 16 * LDSU + kk));
            #pragma unroll
            for (int mt = 0; mt < 4; mt++)
                #pragma unroll
                for (int nt = 0; nt < 4; nt++)
                    mma_f16(acc[mt][nt], afr[mt], &b4[nt >> 1][(nt & 1) * 2]);
        }
        slot = (slot == 2) ? 0 : slot + 1;
        nslot = (nslot == 2) ? 0 : nslot + 1;
    }

    #pragma unroll
    for (int mt = 0; mt < 4; mt++) {
        #pragma unroll
        for (int nt = 0; nt < 4; nt++) {
            int row0 = bm + wm + mt * 16 + g;
            int col  = bn + wn + nt * 8 + t * 2;
            float b0 = bias[col], b1 = bias[col + 1];
            g_reg[(size_t)row0 * DH + col]           = acc[mt][nt][0] + b0;
            g_reg[(size_t)row0 * DH + col + 1]       = acc[mt][nt][1] + b1;
            g_reg[(size_t)(row0 + 8) * DH + col]     = acc[mt][nt][2] + b0;
            g_reg[(size_t)(row0 + 8) * DH + col + 1] = acc[mt][nt][3] + b1;
        }
    }
}

// =====================================================================
// Stage 2: LayerNorm (warp/row), fp16 output
// =====================================================================
__global__ __launch_bounds__(256) void ln_kernel(
    const float* __restrict__ gamma, const float* __restrict__ beta)
{
    int wglob = (blockIdx.x * blockDim.x + threadIdx.x) >> 5;
    int lane  = threadIdx.x & 31;
    if (wglob >= MTOT) return;
    int c = wglob & 3;
    const float2* row2 = (const float2*)(g_reg + (size_t)wglob * DH);
    float2 v[8]; float s = 0.f, s2 = 0.f;
    #pragma unroll
    for (int i = 0; i < 8; i++) {
        v[i] = row2[lane + i * 32];
        s += v[i].x + v[i].y;
        s2 += v[i].x * v[i].x + v[i].y * v[i].y;
    }
    #pragma unroll
    for (int o = 16; o > 0; o >>= 1) {
        s  += __shfl_xor_sync(0xffffffffu, s,  o);
        s2 += __shfl_xor_sync(0xffffffffu, s2, o);
    }
    float mu   = s * (1.f / DH);
    float var  = s2 * (1.f / DH) - mu * mu;
    float rstd = rsqrtf(var + 1e-5f);
    __half2* orow = (__half2*)(g_xn16 + (size_t)wglob * DH);
    const float2* ga2 = (const float2*)(gamma + c * DH);
    const float2* be2 = (const float2*)(beta  + c * DH);
    #pragma unroll
    for (int i = 0; i < 8; i++) {
        int idx = lane + i * 32;
        float2 ga = ga2[idx], be = be2[idx];
        float x0 = (v[i].x - mu) * rstd * ga.x + be.x;
        float x1 = (v[i].y - mu) * rstd * ga.y + be.y;
        orow[idx] = __floats2half2_rn(x0, x1);
    }
}

// =====================================================================
// Stage 3: per-camera dual GEMM + SwiGLU. BM=128, BN=64, BK=64h. NK=8.
// 3-stage, 1 barrier/tile, ldmatrix loads.
// =====================================================================
__global__ __launch_bounds__(256, 2) void gemm2_kernel()
{
    extern __shared__ __align__(16) unsigned smb2[];
    unsigned* As  = smb2;                       // [3][128*LDSU]
    unsigned* Bgs = smb2 + 3 * 128 * LDSU;      // [3][64*LDSU]
    unsigned* Bvs = Bgs + 3 * 64 * LDSU;        // [3][64*LDSU]

    int tid  = threadIdx.x;
    int bm   = blockIdx.y * 128;
    int bn   = blockIdx.x * 64;
    int c    = blockIdx.z;
    int warp = tid >> 5, lane = tid & 31;
    int wr = warp >> 1, wc = warp & 1;
    int wm = wr * 32,  wn = wc * 32;
    int g = lane >> 2, t = lane & 3;

    float accg[2][4][4], accv[2][4][4];
    #pragma unroll
    for (int i = 0; i < 2; i++)
        #pragma unroll
        for (int j = 0; j < 4; j++)
            #pragma unroll
            for (int k = 0; k < 4; k++) { accg[i][j][k] = 0.f; accv[i][j][k] = 0.f; }

    int lrow = tid >> 3;
    int lcu  = (tid & 7) * 4;
    int lch  = (tid & 7) * 8;
    const __half* wg0 = g_wg16 + (size_t)c * DH * DH;
    const __half* wv0 = g_wv16 + (size_t)c * DH * DH;
    const int NK = DH / 64;   // 8

    const unsigned sAs = (unsigned)__cvta_generic_to_shared(As);
    const unsigned sGs = (unsigned)__cvta_generic_to_shared(Bgs);
    const unsigned sVs = (unsigned)__cvta_generic_to_shared(Bvs);
    const unsigned aLane = sAs + 4u * (unsigned)(wm * LDSU + A_LANE_OFF(lane));
    const unsigned gLane = sGs + 4u * (unsigned)(wn * LDSU + B_LANE_OFF(lane));
    const unsigned vLane = sVs + 4u * (unsigned)(wn * LDSU + B_LANE_OFF(lane));

    #pragma unroll
    for (int s = 0; s < 2; s++) {
        int k0 = s * 64;
        unsigned* dA = As  + s * 128 * LDSU;
        unsigned* dG = Bgs + s * 64 * LDSU;
        unsigned* dV = Bvs + s * 64 * LDSU;
        #pragma unroll
        for (int it = 0; it < 4; it++) {
            int r = lrow + it * 32;
            cp16(&dA[r * LDSU + lcu], g_xn16 + ((size_t)(bm + r) * 4 + c) * DH + k0 + lch);
        }
        #pragma unroll
        for (int it = 0; it < 2; it++) {
            int r = lrow + it * 32;
            cp16(&dG[r * LDSU + lcu], wg0 + (size_t)(bn + r) * DH + k0 + lch);
            cp16(&dV[r * LDSU + lcu], wv0 + (size_t)(bn + r) * DH + k0 + lch);
        }
        cp_commit();
    }

    int slot = 0, nslot = 2;
    for (int i = 0; i < NK; i++) {
        cp_wait1();
        __syncthreads();

        if (i + 2 < NK) {
            int k0 = (i + 2) * 64;
            unsigned* dA = As  + nslot * 128 * LDSU;
            unsigned* dG = Bgs + nslot * 64 * LDSU;
            unsigned* dV = Bvs + nslot * 64 * LDSU;
            #pragma unroll
            for (int it = 0; it < 4; it++) {
                int r = lrow + it * 32;
                cp16(&dA[r * LDSU + lcu], g_xn16 + ((size_t)(bm + r) * 4 + c) * DH + k0 + lch);
            }
            #pragma unroll
            for (int it = 0; it < 2; it++) {
                int r = lrow + it * 32;
                cp16(&dG[r * LDSU + lcu], wg0 + (size_t)(bn + r) * DH + k0 + lch);
                cp16(&dV[r * LDSU + lcu], wv0 + (size_t)(bn + r) * DH + k0 + lch);
            }
        }
        cp_commit();

        unsigned aBase = aLane + 4u * (unsigned)(slot * 128 * LDSU);
        unsigned gBase = gLane + 4u * (unsigned)(slot * 64 * LDSU);
        unsigned vBase = vLane + 4u * (unsigned)(slot * 64 * LDSU);
        #pragma unroll
        for (int kk = 0; kk < 32; kk += 8) {
            unsigned afr[2][4], g4[2][4], v4[2][4];
            #pragma unroll
            for (int mt = 0; mt < 2; mt++)
                ldsm4(afr[mt], aBase + 4u * (unsigned)(mt * 16 * LDSU + kk));
            #pragma unroll
            for (int p = 0; p < 2; p++) {
                ldsm4(g4[p], gBase + 4u * (unsigned)(p * 16 * LDSU + kk));
                ldsm4(v4[p], vBase + 4u * (unsigned)(p * 16 * LDSU + kk));
            }
            #pragma unroll
            for (int mt = 0; mt < 2; mt++)
                #pragma unroll
                for (int nt = 0; nt < 4; nt++) {
                    mma_f16(accg[mt][nt], afr[mt], &g4[nt >> 1][(nt & 1) * 2]);
                    mma_f16(accv[mt][nt], afr[mt], &v4[nt >> 1][(nt & 1) * 2]);
                }
        }
        slot = (slot == 2) ? 0 : slot + 1;
        nslot = (nslot == 2) ? 0 : nslot + 1;
    }

    #pragma unroll
    for (int mt = 0; mt < 2; mt++) {
        #pragma unroll
        for (int nt = 0; nt < 4; nt++) {
            int row0 = bm + wm + mt * 16 + g;
            int col  = bn + wn + nt * 8 + t * 2;
            #pragma unroll
            for (int half = 0; half < 2; half++) {
                int rr = row0 + half * 8;
                float gte0 = accg[mt][nt][half * 2 + 0];
                float gte1 = accg[mt][nt][half * 2 + 1];
                float val0 = accv[mt][nt][half * 2 + 0];
                float val1 = accv[mt][nt][half * 2 + 1];
                float h0 = gte0 / (1.f + expf(-gte0)) * val0;
                float h1 = gte1 / (1.f + expf(-gte1)) * val1;
                __half2* dst = (__half2*)(g_h16 + ((size_t)rr * 4 + c) * DH + col);
                *dst = __floats2half2_rn(h0, h1);
            }
        }
    }
}

// =====================================================================
// Stage 4: per-camera A = h16 @ wo16^T. BK=64h, 2-stage, ldmatrix.
// =====================================================================
__global__ __launch_bounds__(256, 2) void gemm3_kernel()
{
    extern __shared__ __align__(16) unsigned smb3[];
    unsigned* As = smb3;                     // [2][128*LDSU]
    unsigned* Bs = smb3 + 2 * 128 * LDSU;    // [2][40*LDSU]

    int tid  = threadIdx.x;
    int bm   = blockIdx.y * 128;
    int c    = blockIdx.z;
    int warp = tid >> 5, lane = tid & 31;
    int wm   = warp * 16;
    int g = lane >> 2, t = lane & 3;

    for (int i = tid; i < 2 * 4 * LDSU; i += 256) {
        int b = i / (4 * LDSU);
        int rem = i % (4 * LDSU);
        Bs[b * 40 * LDSU + 36 * LDSU + rem] = 0u;
    }

    float acc[5][4];
    #pragma unroll
    for (int j = 0; j < 5; j++)
        #pragma unroll
        for (int k = 0; k < 4; k++) acc[j][k] = 0.f;

    int lrow = tid >> 3;
    int lcu  = (tid & 7) * 4;
    int lch  = (tid & 7) * 8;
    const __half* wo0 = g_wo16 + (size_t)c * 36 * DH;
    const int NK = DH / 64;   // 8

    const unsigned sAs = (unsigned)__cvta_generic_to_shared(As);
    const unsigned sBs = (unsigned)__cvta_generic_to_shared(Bs);
    const unsigned aLane  = sAs + 4u * (unsigned)(wm * LDSU + A_LANE_OFF(lane));
    const unsigned bLane  = sBs + 4u * (unsigned)(B_LANE_OFF(lane));
    const unsigned b2Lane = sBs + 4u * (unsigned)(32 * LDSU + B2_LANE_OFF(lane));

    {
        #pragma unroll
        for (int it = 0; it < 4; it++) {
            int r = lrow + it * 32;
            cp16(&As[r * LDSU + lcu], g_h16 + ((size_t)(bm + r) * 4 + c) * DH + lch);
        }
        for (int i2 = tid; i2 < 288; i2 += 256) {
            int r = i2 >> 3, cu = (i2 & 7) * 4;
            cp16(&Bs[r * LDSU + cu], wo0 + (size_t)r * DH + (i2 & 7) * 8);
        }
        cp_commit();
    }

    for (int i = 0; i < NK; i++) {
        if (i + 1 < NK) {
            int k0 = (i + 1) * 64;
            int b = (i + 1) & 1;
            unsigned* dA = As + b * 128 * LDSU;
            unsigned* dB = Bs + b * 40 * LDSU;
            #pragma unroll
            for (int it = 0; it < 4; it++) {
                int r = lrow + it * 32;
                cp16(&dA[r * LDSU + lcu], g_h16 + ((size_t)(bm + r) * 4 + c) * DH + k0 + lch);
            }
            for (int i2 = tid; i2 < 288; i2 += 256) {
                int r = i2 >> 3, cu = (i2 & 7) * 4;
                cp16(&dB[r * LDSU + cu], wo0 + (size_t)r * DH + k0 + (i2 & 7) * 8);
            }
            cp_commit(); cp_wait1();
        } else {
            cp_wait0();
        }
        __syncthreads();

        int b = i & 1;
        unsigned aBase = aLane  + 4u * (unsigned)(b * 128 * LDSU);
        unsigned bBase = bLane  + 4u * (unsigned)(b * 40 * LDSU);
        unsigned cBase = b2Lane + 4u * (unsigned)(b * 40 * LDSU);
        #pragma unroll
        for (int kk = 0; kk < 32; kk += 8) {
            unsigned afr[4], b4[2][4], b2[2];
            ldsm4(afr, aBase + 4u * (unsigned)kk);
            #pragma unroll
            for (int p = 0; p < 2; p++)
                ldsm4(b4[p], bBase + 4u * (unsigned)(p * 16 * LDSU + kk));
            ldsm2(b2, cBase + 4u * (unsigned)kk);
            #pragma unroll
            for (int nt = 0; nt < 4; nt++)
                mma_f16(acc[nt], afr, &b4[nt >> 1][(nt & 1) * 2]);
            mma_f16(acc[4], afr, b2);
        }
        __syncthreads();
    }

    #pragma unroll
    for (int nt = 0; nt < 5; nt++) {
        int col = nt * 8 + t * 2;
        if (col < 36) {
            int row0 = bm + wm + g;
            size_t base0 = ((size_t)row0 * 4 + c) * 36;
            size_t base1 = ((size_t)(row0 + 8) * 4 + c) * 36;
            g_A[base0 + col]     = acc[nt][0];
            g_A[base0 + col + 1] = acc[nt][1];
            g_A[base1 + col]     = acc[nt][2];
            g_A[base1 + col + 1] = acc[nt][3];
        }
    }
}

// =====================================================================
// Stage 5: skew + clip + expm (scale-square Taylor 12), out[C,B,6,6]
// =====================================================================
__global__ __launch_bounds__(128) void expm_kernel(float* __restrict__ out)
{
    int m = blockIdx.x * blockDim.x + threadIdx.x;
    if (m >= MTOT) return;
    int c = m & 3, b = m >> 2;

    const float* src = g_A + (size_t)m * 36;
    float raw[36];
    #pragma unroll
    for (int i = 0; i < 36; i++) raw[i] = src[i];

    float A[36]; float ss = 0.f;
    #pragma unroll
    for (int i = 0; i < 6; i++)
        #pragma unroll
        for (int j = 0; j < 6; j++) {
            float v = raw[i * 6 + j] - raw[j * 6 + i];
            A[i * 6 + j] = v; ss += v * v;
        }
    float frob  = sqrtf(ss);
    float scale = fminf(frob, 3.0f) / fmaxf(frob, 1e-8f);

    float As[36];
    #pragma unroll
    for (int i = 0; i < 36; i++) As[i] = A[i] * scale * 0.0625f;

    float E[36], term[36];
    #pragma unroll
    for (int i = 0; i < 36; i++) { E[i] = (i % 7 == 0) ? 1.f : 0.f; term[i] = E[i]; }

    #pragma unroll 1
    for (int k = 1; k <= 12; k++) {
        float nt[36];
        float inv = 1.f / (float)k;
        #pragma unroll
        for (int i = 0; i < 6; i++)
            #pragma unroll
            for (int j = 0; j < 6; j++) {
                float sacc = 0.f;
                #pragma unroll
                for (int l = 0; l < 6; l++) sacc += term[i * 6 + l] * As[l * 6 + j];
                nt[i * 6 + j] = sacc * inv;
            }
        #pragma unroll
        for (int i = 0; i < 36; i++) { term[i] = nt[i]; E[i] += nt[i]; }
    }
    #pragma unroll 1
    for (int s = 0; s < 4; s++) {
        float nt[36];
        #pragma unroll
        for (int i = 0; i < 6; i++)
            #pragma unroll
            for (int j = 0; j < 6; j++) {
                float sacc = 0.f;
                #pragma unroll
                for (int l = 0; l < 6; l++) sacc += E[i * 6 + l] * E[l * 6 + j];
                nt[i * 6 + j] = sacc;
            }
        #pragma unroll
        for (int i = 0; i < 36; i++) E[i] = nt[i];
    }

    float* dst = out + ((size_t)c * B_SZ + b) * 36;
    #pragma unroll
    for (int i = 0; i < 36; i++) dst[i] = E[i];
}

// =====================================================================
extern "C" void kernel_launch(void* const* d_in, const int* in_sizes, int n_in,
                              void* d_out, int out_size)
{
    const float* thumb  = (const float*)d_in[0];
    const float* proj_w = (const float*)d_in[1];
    const float* proj_b = (const float*)d_in[2];
    const float* gamma  = (const float*)d_in[3];
    const float* beta   = (const float*)d_in[4];
    const float* w_gate = (const float*)d_in[5];
    const float* w_val  = (const float*)d_in[6];
    const float* w_out  = (const float*)d_in[7];
    float* out = (float*)d_out;

    (void)in_sizes; (void)n_in; (void)out_size;

    const int SM1 = 3 * 2 * 128 * LDSU * 4;                 // 110592
    const int SM2 = (3 * 128 * LDSU + 6 * 64 * LDSU) * 4;   // 110592
    const int SM3 = (2 * 128 * LDSU + 2 * 40 * LDSU) * 4;   // 48384

    cudaFuncSetAttribute(gemm1_kernel, cudaFuncAttributeMaxDynamicSharedMemorySize, SM1);
    cudaFuncSetAttribute(gemm2_kernel, cudaFuncAttributeMaxDynamicSharedMemorySize, SM2);
    cudaFuncSetAttribute(gemm3_kernel, cudaFuncAttributeMaxDynamicSharedMemorySize, SM3);

    conv_thumb<<<65536, 256>>>(thumb);
    round_weights<<<4384, 256>>>(proj_w, w_gate, w_val, w_out);
    gemm1_kernel<<<dim3(4, 512), 256, SM1>>>(proj_b);
    ln_kernel<<<MTOT / 8, 256>>>(gamma, beta);
    gemm2_kernel<<<dim3(8, 128, 4), 256, SM2>>>();
    gemm3_kernel<<<dim3(1, 128, 4), 256, SM3>>>();
    expm_kernel<<<MTOT / 128, 128>>>(out);
}